// round 9
// baseline (speedup 1.0000x reference)
#include <cuda_runtime.h>
#include <cuda_bf16.h>
#include <float.h>

#define Bn   4
#define Nn   8192
#define Cc   256
#define Kk   16
#define Ff   512
#define ROWS (Bn*Nn)
#define CAP  128         // append-buffer capacity per query

typedef unsigned long long ull;

__device__ float4 g_pos4 [ROWS];
__device__ float4 g_pos4s[ROWS];
__device__ int    g_sid  [ROWS];
__device__ int    g_ovf  [ROWS];
__device__ float  g_M[Cc * Ff];
__device__ float  g_Y[(size_t)ROWS * Ff];
__device__ int    g_idx[ROWS * Kk];

#define FMA2(acc, a, b) \
    asm("fma.rn.f32x2 %0, %1, %2, %3;" : "=l"(acc) : "l"(a), "l"(b), "l"(acc))
#define PACK2(out, lo, hi) \
    asm("mov.b64 %0, {%1, %2};" : "=l"(out) : "f"(lo), "f"(hi))
#define UNPACK2(lo, hi, in) \
    asm("mov.b64 {%0, %1}, %2;" : "=f"(lo), "=f"(hi) : "l"(in))

// ---------------------------------------------------------------------------
__global__ void prep_pos_kernel(const float* __restrict__ qpos) {
    int i = blockIdx.x * blockDim.x + threadIdx.x;
    if (i >= ROWS) return;
    float x = qpos[i*3+0], y = qpos[i*3+1], z = qpos[i*3+2];
    float n = fmaf(z, z, fmaf(y, y, x * x));
    g_pos4[i] = make_float4(x, y, z, n);
}

__global__ void prep_M_kernel(const float* __restrict__ W) {
    int i = blockIdx.x * blockDim.x + threadIdx.x;
    if (i >= Cc * Ff) return;
    int r = i / Ff;
    int c = i % Ff;
    float v;
    if (c < Cc) v = W[r * Cc + c];
    else        v = W[(Cc + r) * Cc + (c - Cc)] - W[r * Cc + (c - Cc)];
    g_M[i] = v;
}

// ---------------------------------------------------------------------------
__global__ __launch_bounds__(512) void sort_kernel() {
    const int b   = blockIdx.x;
    const int tid = threadIdx.x;
    __shared__ unsigned sk[Nn];          // 32 KB

    for (int i = tid; i < Nn; i += 512) {
        unsigned u = __float_as_uint(g_pos4[b*Nn + i].x);
        u = (u & 0x80000000u) ? ~u : (u | 0x80000000u);
        sk[i] = (u & 0xFFFFE000u) | (unsigned)i;
    }
    __syncthreads();

    for (int k = 2; k <= Nn; k <<= 1) {
        for (int j = k >> 1; j > 0; j >>= 1) {
            for (int t = tid; t < Nn/2; t += 512) {
                int i   = 2*t - (t & (j - 1));
                int ixj = i + j;
                unsigned a = sk[i], c = sk[ixj];
                bool asc = ((i & k) == 0);
                if ((a > c) == asc) { sk[i] = c; sk[ixj] = a; }
            }
            __syncthreads();
        }
    }

    for (int i = tid; i < Nn; i += 512) {
        int orig = (int)(sk[i] & 8191u);
        g_pos4s[b*Nn + i] = g_pos4[b*Nn + orig];
        g_sid  [b*Nn + i] = orig;
    }
}

// ---------------------------------------------------------------------------
// KNN v3 (unchanged from round 8): warp owns 4 queries; lane scans 1/32.
// ---------------------------------------------------------------------------
__global__ __launch_bounds__(256) void knn_kernel() {
    const int b    = blockIdx.y;
    const int tid  = threadIdx.x;
    const int w    = tid >> 5;
    const int lane = tid & 31;
    const int qb   = blockIdx.x * 32 + w * 4;

    const float4* __restrict__ pos = g_pos4s + b * Nn;
    const int*    __restrict__ sid = g_sid   + b * Nn;

    __shared__ float4         tile[1024];
    __shared__ float          ad[32][CAP];
    __shared__ unsigned short ai[32][CAP];
    __shared__ int            acnt[32];

    float qx[4], qy[4], qz[4];
#pragma unroll
    for (int i = 0; i < 4; ++i) {
        float4 m = pos[qb + i];
        qx[i] = m.x; qy[i] = m.y; qz[i] = m.z;
    }

    const int ctile = blockIdx.x >> 5;

    if (tid < 32) acnt[tid] = 0;
    {
        const int t0 = ctile * 1024;
#pragma unroll
        for (int j = 0; j < 4; ++j)
            tile[tid + j * 256] = pos[t0 + tid + j * 256];
    }
    __syncthreads();

    float t1[4], t2[4];
#pragma unroll
    for (int i = 0; i < 4; ++i) { t1[i] = FLT_MAX; t2[i] = FLT_MAX; }

    for (int m = 0; m < 32; m += 4) {
        float4 c0 = tile[lane + (m + 0) * 32];
        float4 c1 = tile[lane + (m + 1) * 32];
        float4 c2 = tile[lane + (m + 2) * 32];
        float4 c3 = tile[lane + (m + 3) * 32];
#pragma unroll
        for (int i = 0; i < 4; ++i) {
            float d0 = fmaf(-2.0f, fmaf(qz[i], c0.z, fmaf(qy[i], c0.y, qx[i] * c0.x)), c0.w);
            float d1 = fmaf(-2.0f, fmaf(qz[i], c1.z, fmaf(qy[i], c1.y, qx[i] * c1.x)), c1.w);
            float d2 = fmaf(-2.0f, fmaf(qz[i], c2.z, fmaf(qy[i], c2.y, qx[i] * c2.x)), c2.w);
            float d3 = fmaf(-2.0f, fmaf(qz[i], c3.z, fmaf(qy[i], c3.y, qx[i] * c3.x)), c3.w);
            float mn01 = fminf(d0, d1), mx01 = fmaxf(d0, d1);
            float mn23 = fminf(d2, d3), mx23 = fmaxf(d2, d3);
            float s1 = fminf(mn01, mn23);
            float s2 = fminf(fmaxf(mn01, mn23), fminf(mx01, mx23));
            float nt1 = fminf(t1[i], s1);
            t2[i] = fminf(fmaxf(t1[i], s1), fminf(t2[i], s2));
            t1[i] = nt1;
        }
    }

    float thr[4];
#pragma unroll
    for (int i = 0; i < 4; ++i) {
        float a = t1[i], bb = t2[i];
        float m = FLT_MAX;
        for (int r = 0; r < 16; ++r) {
            float lo = fminf(a, bb);
            m = lo;
            m = fminf(m, __shfl_xor_sync(0xffffffffu, m, 1));
            m = fminf(m, __shfl_xor_sync(0xffffffffu, m, 2));
            m = fminf(m, __shfl_xor_sync(0xffffffffu, m, 4));
            m = fminf(m, __shfl_xor_sync(0xffffffffu, m, 8));
            m = fminf(m, __shfl_xor_sync(0xffffffffu, m, 16));
            unsigned msk = __ballot_sync(0xffffffffu, lo == m);
            int leader = __ffs(msk) - 1;
            if (lane == leader) {
                if (a <= bb) a = FLT_MAX; else bb = FLT_MAX;
            }
        }
        thr[i] = m;
    }

    for (int ot = 0; ot < 8; ++ot) {
        const int tt = (ctile + ot) & 7;
        const int t0 = tt * 1024;
        if (ot > 0) {
            __syncthreads();
#pragma unroll
            for (int j = 0; j < 4; ++j)
                tile[tid + j * 256] = pos[t0 + tid + j * 256];
            __syncthreads();
        }
        for (int m = 0; m < 32; m += 4) {
            float4 c0 = tile[lane + (m + 0) * 32];
            float4 c1 = tile[lane + (m + 1) * 32];
            float4 c2 = tile[lane + (m + 2) * 32];
            float4 c3 = tile[lane + (m + 3) * 32];
#pragma unroll
            for (int i = 0; i < 4; ++i) {
                float d0 = fmaf(-2.0f, fmaf(qz[i], c0.z, fmaf(qy[i], c0.y, qx[i] * c0.x)), c0.w);
                float d1 = fmaf(-2.0f, fmaf(qz[i], c1.z, fmaf(qy[i], c1.y, qx[i] * c1.x)), c1.w);
                float d2 = fmaf(-2.0f, fmaf(qz[i], c2.z, fmaf(qy[i], c2.y, qx[i] * c2.x)), c2.w);
                float d3 = fmaf(-2.0f, fmaf(qz[i], c3.z, fmaf(qy[i], c3.y, qx[i] * c3.x)), c3.w);
                float mn = fminf(fminf(d0, d1), fminf(d2, d3));
                if (mn <= thr[i]) {
                    const int ql = w * 4 + i;
                    const int jb = t0 + lane + m * 32;
                    if (d0 <= thr[i]) {
                        int sl = atomicAdd(&acnt[ql], 1);
                        if (sl < CAP) { ad[ql][sl] = d0; ai[ql][sl] = (unsigned short)(jb); }
                    }
                    if (d1 <= thr[i]) {
                        int sl = atomicAdd(&acnt[ql], 1);
                        if (sl < CAP) { ad[ql][sl] = d1; ai[ql][sl] = (unsigned short)(jb + 32); }
                    }
                    if (d2 <= thr[i]) {
                        int sl = atomicAdd(&acnt[ql], 1);
                        if (sl < CAP) { ad[ql][sl] = d2; ai[ql][sl] = (unsigned short)(jb + 64); }
                    }
                    if (d3 <= thr[i]) {
                        int sl = atomicAdd(&acnt[ql], 1);
                        if (sl < CAP) { ad[ql][sl] = d3; ai[ql][sl] = (unsigned short)(jb + 96); }
                    }
                }
            }
        }
    }
    __syncthreads();

    if (tid < 32) {
        const int cntRaw = acnt[tid];
        const int cnt    = cntRaw < CAP ? cntRaw : CAP;
        float md[Kk]; int mi[Kk];
#pragma unroll
        for (int i = 0; i < Kk; ++i) { md[i] = FLT_MAX; mi[i] = 0; }
        float mthr = FLT_MAX;
        for (int t = 0; t < cnt; ++t) {
            float cd = ad[tid][t];
            if (cd < mthr) {
                int ci = ai[tid][t];
#pragma unroll
                for (int u = 0; u < Kk; ++u) {
                    bool  sw = cd < md[u];
                    float od = md[u]; int oi = mi[u];
                    md[u] = sw ? cd : od;  mi[u] = sw ? ci : oi;
                    cd    = sw ? od : cd;  ci    = sw ? oi : ci;
                }
                mthr = md[Kk - 1];
            }
        }
        const int orig = sid[blockIdx.x * 32 + tid];
        const int gq   = b * Nn + orig;
        g_ovf[gq] = (cntRaw > CAP) ? 1 : 0;
#pragma unroll
        for (int i = 0; i < Kk; ++i) g_idx[gq * Kk + i] = sid[mi[i]];
    }
}

// ---------------------------------------------------------------------------
__global__ __launch_bounds__(256) void knn_fix_kernel() {
    const int i = blockIdx.x * 256 + threadIdx.x;
    if (i >= ROWS) return;
    if (!g_ovf[i]) return;
    const int b = i >> 13;
    const float4* __restrict__ pos = g_pos4 + b * Nn;
    float4 me = pos[i & 8191];
    const float qx = me.x, qy = me.y, qz = me.z;
    float dist[Kk]; int nid[Kk];
#pragma unroll
    for (int t = 0; t < Kk; ++t) { dist[t] = FLT_MAX; nid[t] = 0; }
    float thr = FLT_MAX;
    for (int j = 0; j < Nn; ++j) {
        float4 cp = pos[j];
        float d2 = fmaf(-2.0f, fmaf(qz, cp.z, fmaf(qy, cp.y, qx * cp.x)), cp.w);
        if (d2 < thr) {
            float cd = d2; int ci = j;
#pragma unroll
            for (int t = 0; t < Kk; ++t) {
                bool  sw = cd < dist[t];
                float od = dist[t]; int oi = nid[t];
                dist[t] = sw ? cd : od;  nid[t] = sw ? ci : oi;
                cd      = sw ? od : cd;  ci     = sw ? oi : ci;
            }
            thr = dist[Kk - 1];
        }
    }
#pragma unroll
    for (int t = 0; t < Kk; ++t) g_idx[i * Kk + t] = nid[t];
}

// ---------------------------------------------------------------------------
// SGEMM v2: f32x2 packed FFMA2. Rows paired into f32x2 lanes (A pairs free
// from row-contiguous As); B stored duplicated (splat pairs free via LDS.128).
// Bit-identical to scalar FFMA version.
// ---------------------------------------------------------------------------
__global__ __launch_bounds__(256, 2) void sgemm_kernel(const float* __restrict__ A) {
    __shared__ float As[16][128];     // 8 KB  (col-major: [kk][row])
    __shared__ ull   Bs2[16][128];    // 16 KB (duplicated: {b,b} per col)

    const int tid  = threadIdx.x;
    const int bm0  = blockIdx.y * 128;
    const int bn0  = blockIdx.x * 128;

    const int arow = tid >> 2;
    const int acol = (tid & 3) * 4;
    const int brow = tid >> 5;
    const int bcol = (tid & 31) * 4;

    const int tx = tid & 15, ty = tid >> 4;
    const int c0 = tx * 4, c1 = 64 + tx * 4;
    const int r0 = ty * 4, r1 = 64 + ty * 4;

    // acc[rp][j]: rp=row-pair (0:{r0,r0+1} 1:{r0+2,r0+3} 2:{r1,r1+1} 3:{r1+2,r1+3})
    // j = col index into {c0..c0+3, c1..c1+3}
    ull acc[4][8];
#pragma unroll
    for (int i = 0; i < 4; ++i)
#pragma unroll
        for (int j = 0; j < 8; ++j) acc[i][j] = 0ull;

    for (int kt = 0; kt < Cc; kt += 16) {
        float4 a0 = *(const float4*)(A + (size_t)(bm0 + arow)      * Cc + kt + acol);
        float4 a1 = *(const float4*)(A + (size_t)(bm0 + arow + 64) * Cc + kt + acol);
        float4 b0 = *(const float4*)(g_M + (size_t)(kt + brow)     * Ff + bn0 + bcol);
        float4 b1 = *(const float4*)(g_M + (size_t)(kt + brow + 8) * Ff + bn0 + bcol);

        __syncthreads();
        As[acol + 0][arow] = a0.x; As[acol + 1][arow] = a0.y;
        As[acol + 2][arow] = a0.z; As[acol + 3][arow] = a0.w;
        As[acol + 0][arow + 64] = a1.x; As[acol + 1][arow + 64] = a1.y;
        As[acol + 2][arow + 64] = a1.z; As[acol + 3][arow + 64] = a1.w;
        {
            ull p;
            PACK2(p, b0.x, b0.x); Bs2[brow][bcol + 0] = p;
            PACK2(p, b0.y, b0.y); Bs2[brow][bcol + 1] = p;
            PACK2(p, b0.z, b0.z); Bs2[brow][bcol + 2] = p;
            PACK2(p, b0.w, b0.w); Bs2[brow][bcol + 3] = p;
            PACK2(p, b1.x, b1.x); Bs2[brow + 8][bcol + 0] = p;
            PACK2(p, b1.y, b1.y); Bs2[brow + 8][bcol + 1] = p;
            PACK2(p, b1.z, b1.z); Bs2[brow + 8][bcol + 2] = p;
            PACK2(p, b1.w, b1.w); Bs2[brow + 8][bcol + 3] = p;
        }
        __syncthreads();

#pragma unroll
        for (int kk = 0; kk < 16; ++kk) {
            longlong2 av0 = *(const longlong2*)&As[kk][r0];   // rows r0..r0+3
            longlong2 av1 = *(const longlong2*)&As[kk][r1];   // rows r1..r1+3
            longlong2 bv0 = *(const longlong2*)&Bs2[kk][c0];
            longlong2 bv1 = *(const longlong2*)&Bs2[kk][c0 + 2];
            longlong2 bv2 = *(const longlong2*)&Bs2[kk][c1];
            longlong2 bv3 = *(const longlong2*)&Bs2[kk][c1 + 2];
            ull ap[4] = {(ull)av0.x, (ull)av0.y, (ull)av1.x, (ull)av1.y};
            ull bs[8] = {(ull)bv0.x, (ull)bv0.y, (ull)bv1.x, (ull)bv1.y,
                         (ull)bv2.x, (ull)bv2.y, (ull)bv3.x, (ull)bv3.y};
#pragma unroll
            for (int i = 0; i < 4; ++i)
#pragma unroll
                for (int j = 0; j < 8; ++j)
                    FMA2(acc[i][j], ap[i], bs[j]);
        }
    }

    // epilogue: unpack row-pairs, store float4 per row
#pragma unroll
    for (int rp = 0; rp < 4; ++rp) {
        const int row_lo = (rp < 2) ? (r0 + 2 * rp) : (r1 + 2 * (rp - 2));
        float lo[8], hi[8];
#pragma unroll
        for (int j = 0; j < 8; ++j) UNPACK2(lo[j], hi[j], acc[rp][j]);
        *(float4*)(g_Y + (size_t)(bm0 + row_lo)     * Ff + bn0 + c0) = make_float4(lo[0], lo[1], lo[2], lo[3]);
        *(float4*)(g_Y + (size_t)(bm0 + row_lo)     * Ff + bn0 + c1) = make_float4(lo[4], lo[5], lo[6], lo[7]);
        *(float4*)(g_Y + (size_t)(bm0 + row_lo + 1) * Ff + bn0 + c0) = make_float4(hi[0], hi[1], hi[2], hi[3]);
        *(float4*)(g_Y + (size_t)(bm0 + row_lo + 1) * Ff + bn0 + c1) = make_float4(hi[4], hi[5], hi[6], hi[7]);
    }
}

// ---------------------------------------------------------------------------
__global__ __launch_bounds__(256) void gather_max_kernel(const float* __restrict__ bias,
                                                         float* __restrict__ out) {
    const int row  = blockIdx.x * 8 + (threadIdx.x >> 5);
    const int lane = threadIdx.x & 31;
    const int b    = row >> 13;

    const int* ir = g_idx + row * Kk;
    int myn = ir[lane & (Kk - 1)];

    const float* Ybase = g_Y + (size_t)(b << 13) * Ff;

    float4 m0 = make_float4(-FLT_MAX, -FLT_MAX, -FLT_MAX, -FLT_MAX);
    float4 m1 = m0;

#pragma unroll
    for (int j = 0; j < Kk; ++j) {
        int nb = __shfl_sync(0xffffffffu, myn, j);
        const float4* Pr = (const float4*)(Ybase + (size_t)nb * Ff);
        float4 a = Pr[lane];
        float4 c = Pr[lane + 32];
        m0.x = fmaxf(m0.x, a.x); m0.y = fmaxf(m0.y, a.y);
        m0.z = fmaxf(m0.z, a.z); m0.w = fmaxf(m0.w, a.w);
        m1.x = fmaxf(m1.x, c.x); m1.y = fmaxf(m1.y, c.y);
        m1.z = fmaxf(m1.z, c.z); m1.w = fmaxf(m1.w, c.w);
    }

    const float4* Ur = (const float4*)(g_Y + (size_t)row * Ff + Cc);
    float4 u0 = Ur[lane], u1 = Ur[lane + 32];
    const float4* Br = (const float4*)bias;
    float4 bb0 = Br[lane], bb1 = Br[lane + 32];

    float4 v0, v1;
    v0.x = m0.x + u0.x + bb0.x; v0.y = m0.y + u0.y + bb0.y;
    v0.z = m0.z + u0.z + bb0.z; v0.w = m0.w + u0.w + bb0.w;
    v1.x = m1.x + u1.x + bb1.x; v1.y = m1.y + u1.y + bb1.y;
    v1.z = m1.z + u1.z + bb1.z; v1.w = m1.w + u1.w + bb1.w;

    v0.x = fmaxf(v0.x, 0.2f * v0.x); v0.y = fmaxf(v0.y, 0.2f * v0.y);
    v0.z = fmaxf(v0.z, 0.2f * v0.z); v0.w = fmaxf(v0.w, 0.2f * v0.w);
    v1.x = fmaxf(v1.x, 0.2f * v1.x); v1.y = fmaxf(v1.y, 0.2f * v1.y);
    v1.z = fmaxf(v1.z, 0.2f * v1.z); v1.w = fmaxf(v1.w, 0.2f * v1.w);

    float4* Or = (float4*)(out + (size_t)row * Cc);
    Or[lane]      = v0;
    Or[lane + 32] = v1;
}

// ---------------------------------------------------------------------------
extern "C" void kernel_launch(void* const* d_in, const int* in_sizes, int n_in,
                              void* d_out, int out_size) {
    const float* q    = (const float*)d_in[0];   // [4,8192,256]
    const float* qpos = (const float*)d_in[1];   // [4,8192,3]
    const float* W    = (const float*)d_in[2];   // [512,256]
    const float* bias = (const float*)d_in[3];   // [256]
    float* out = (float*)d_out;
    (void)in_sizes; (void)n_in; (void)out_size;

    prep_pos_kernel<<<(ROWS + 255) / 256, 256>>>(qpos);
    sort_kernel<<<Bn, 512>>>();
    prep_M_kernel<<<(Cc * Ff + 255) / 256, 256>>>(W);
    knn_kernel<<<dim3(Nn / 32, Bn), 256>>>();
    knn_fix_kernel<<<ROWS / 256, 256>>>();
    sgemm_kernel<<<dim3(Ff / 128, ROWS / 128), 256>>>(q);
    gather_max_kernel<<<ROWS / 8, 256>>>(bias, out);
}

// round 10
// speedup vs baseline: 1.3944x; 1.3944x over previous
#include <cuda_runtime.h>
#include <cuda_bf16.h>
#include <float.h>

#define Bn   4
#define Nn   8192
#define Cc   256
#define Kk   16
#define Ff   512
#define ROWS (Bn*Nn)
#define CAP  128         // append-buffer capacity per query

__device__ float4 g_pos4 [ROWS];
__device__ float4 g_pos4s[ROWS];
__device__ int    g_sid  [ROWS];
__device__ int    g_ovf  [ROWS];
__device__ float  g_M[Cc * Ff];
__device__ float  g_Y[(size_t)ROWS * Ff];
__device__ int    g_idx[ROWS * Kk];

// ---------------------------------------------------------------------------
__global__ void prep_pos_kernel(const float* __restrict__ qpos) {
    int i = blockIdx.x * blockDim.x + threadIdx.x;
    if (i >= ROWS) return;
    float x = qpos[i*3+0], y = qpos[i*3+1], z = qpos[i*3+2];
    float n = fmaf(z, z, fmaf(y, y, x * x));
    g_pos4[i] = make_float4(x, y, z, n);
}

__global__ void prep_M_kernel(const float* __restrict__ W) {
    int i = blockIdx.x * blockDim.x + threadIdx.x;
    if (i >= Cc * Ff) return;
    int r = i / Ff;
    int c = i % Ff;
    float v;
    if (c < Cc) v = W[r * Cc + c];
    else        v = W[(Cc + r) * Cc + (c - Cc)] - W[r * Cc + (c - Cc)];
    g_M[i] = v;
}

// ---------------------------------------------------------------------------
__global__ __launch_bounds__(512) void sort_kernel() {
    const int b   = blockIdx.x;
    const int tid = threadIdx.x;
    __shared__ unsigned sk[Nn];          // 32 KB

    for (int i = tid; i < Nn; i += 512) {
        unsigned u = __float_as_uint(g_pos4[b*Nn + i].x);
        u = (u & 0x80000000u) ? ~u : (u | 0x80000000u);
        sk[i] = (u & 0xFFFFE000u) | (unsigned)i;
    }
    __syncthreads();

    for (int k = 2; k <= Nn; k <<= 1) {
        for (int j = k >> 1; j > 0; j >>= 1) {
            for (int t = tid; t < Nn/2; t += 512) {
                int i   = 2*t - (t & (j - 1));
                int ixj = i + j;
                unsigned a = sk[i], c = sk[ixj];
                bool asc = ((i & k) == 0);
                if ((a > c) == asc) { sk[i] = c; sk[ixj] = a; }
            }
            __syncthreads();
        }
    }

    for (int i = tid; i < Nn; i += 512) {
        int orig = (int)(sk[i] & 8191u);
        g_pos4s[b*Nn + i] = g_pos4[b*Nn + orig];
        g_sid  [b*Nn + i] = orig;
    }
}

// ---------------------------------------------------------------------------
// KNN v3 (round-8, unchanged): warp owns 4 queries; lane scans 1/32.
// ---------------------------------------------------------------------------
__global__ __launch_bounds__(256) void knn_kernel() {
    const int b    = blockIdx.y;
    const int tid  = threadIdx.x;
    const int w    = tid >> 5;
    const int lane = tid & 31;
    const int qb   = blockIdx.x * 32 + w * 4;

    const float4* __restrict__ pos = g_pos4s + b * Nn;
    const int*    __restrict__ sid = g_sid   + b * Nn;

    __shared__ float4         tile[1024];
    __shared__ float          ad[32][CAP];
    __shared__ unsigned short ai[32][CAP];
    __shared__ int            acnt[32];

    float qx[4], qy[4], qz[4];
#pragma unroll
    for (int i = 0; i < 4; ++i) {
        float4 m = pos[qb + i];
        qx[i] = m.x; qy[i] = m.y; qz[i] = m.z;
    }

    const int ctile = blockIdx.x >> 5;

    if (tid < 32) acnt[tid] = 0;
    {
        const int t0 = ctile * 1024;
#pragma unroll
        for (int j = 0; j < 4; ++j)
            tile[tid + j * 256] = pos[t0 + tid + j * 256];
    }
    __syncthreads();

    float t1[4], t2[4];
#pragma unroll
    for (int i = 0; i < 4; ++i) { t1[i] = FLT_MAX; t2[i] = FLT_MAX; }

    for (int m = 0; m < 32; m += 4) {
        float4 c0 = tile[lane + (m + 0) * 32];
        float4 c1 = tile[lane + (m + 1) * 32];
        float4 c2 = tile[lane + (m + 2) * 32];
        float4 c3 = tile[lane + (m + 3) * 32];
#pragma unroll
        for (int i = 0; i < 4; ++i) {
            float d0 = fmaf(-2.0f, fmaf(qz[i], c0.z, fmaf(qy[i], c0.y, qx[i] * c0.x)), c0.w);
            float d1 = fmaf(-2.0f, fmaf(qz[i], c1.z, fmaf(qy[i], c1.y, qx[i] * c1.x)), c1.w);
            float d2 = fmaf(-2.0f, fmaf(qz[i], c2.z, fmaf(qy[i], c2.y, qx[i] * c2.x)), c2.w);
            float d3 = fmaf(-2.0f, fmaf(qz[i], c3.z, fmaf(qy[i], c3.y, qx[i] * c3.x)), c3.w);
            float mn01 = fminf(d0, d1), mx01 = fmaxf(d0, d1);
            float mn23 = fminf(d2, d3), mx23 = fmaxf(d2, d3);
            float s1 = fminf(mn01, mn23);
            float s2 = fminf(fmaxf(mn01, mn23), fminf(mx01, mx23));
            float nt1 = fminf(t1[i], s1);
            t2[i] = fminf(fmaxf(t1[i], s1), fminf(t2[i], s2));
            t1[i] = nt1;
        }
    }

    float thr[4];
#pragma unroll
    for (int i = 0; i < 4; ++i) {
        float a = t1[i], bb = t2[i];
        float m = FLT_MAX;
        for (int r = 0; r < 16; ++r) {
            float lo = fminf(a, bb);
            m = lo;
            m = fminf(m, __shfl_xor_sync(0xffffffffu, m, 1));
            m = fminf(m, __shfl_xor_sync(0xffffffffu, m, 2));
            m = fminf(m, __shfl_xor_sync(0xffffffffu, m, 4));
            m = fminf(m, __shfl_xor_sync(0xffffffffu, m, 8));
            m = fminf(m, __shfl_xor_sync(0xffffffffu, m, 16));
            unsigned msk = __ballot_sync(0xffffffffu, lo == m);
            int leader = __ffs(msk) - 1;
            if (lane == leader) {
                if (a <= bb) a = FLT_MAX; else bb = FLT_MAX;
            }
        }
        thr[i] = m;
    }

    for (int ot = 0; ot < 8; ++ot) {
        const int tt = (ctile + ot) & 7;
        const int t0 = tt * 1024;
        if (ot > 0) {
            __syncthreads();
#pragma unroll
            for (int j = 0; j < 4; ++j)
                tile[tid + j * 256] = pos[t0 + tid + j * 256];
            __syncthreads();
        }
        for (int m = 0; m < 32; m += 4) {
            float4 c0 = tile[lane + (m + 0) * 32];
            float4 c1 = tile[lane + (m + 1) * 32];
            float4 c2 = tile[lane + (m + 2) * 32];
            float4 c3 = tile[lane + (m + 3) * 32];
#pragma unroll
            for (int i = 0; i < 4; ++i) {
                float d0 = fmaf(-2.0f, fmaf(qz[i], c0.z, fmaf(qy[i], c0.y, qx[i] * c0.x)), c0.w);
                float d1 = fmaf(-2.0f, fmaf(qz[i], c1.z, fmaf(qy[i], c1.y, qx[i] * c1.x)), c1.w);
                float d2 = fmaf(-2.0f, fmaf(qz[i], c2.z, fmaf(qy[i], c2.y, qx[i] * c2.x)), c2.w);
                float d3 = fmaf(-2.0f, fmaf(qz[i], c3.z, fmaf(qy[i], c3.y, qx[i] * c3.x)), c3.w);
                float mn = fminf(fminf(d0, d1), fminf(d2, d3));
                if (mn <= thr[i]) {
                    const int ql = w * 4 + i;
                    const int jb = t0 + lane + m * 32;
                    if (d0 <= thr[i]) {
                        int sl = atomicAdd(&acnt[ql], 1);
                        if (sl < CAP) { ad[ql][sl] = d0; ai[ql][sl] = (unsigned short)(jb); }
                    }
                    if (d1 <= thr[i]) {
                        int sl = atomicAdd(&acnt[ql], 1);
                        if (sl < CAP) { ad[ql][sl] = d1; ai[ql][sl] = (unsigned short)(jb + 32); }
                    }
                    if (d2 <= thr[i]) {
                        int sl = atomicAdd(&acnt[ql], 1);
                        if (sl < CAP) { ad[ql][sl] = d2; ai[ql][sl] = (unsigned short)(jb + 64); }
                    }
                    if (d3 <= thr[i]) {
                        int sl = atomicAdd(&acnt[ql], 1);
                        if (sl < CAP) { ad[ql][sl] = d3; ai[ql][sl] = (unsigned short)(jb + 96); }
                    }
                }
            }
        }
    }
    __syncthreads();

    if (tid < 32) {
        const int cntRaw = acnt[tid];
        const int cnt    = cntRaw < CAP ? cntRaw : CAP;
        float md[Kk]; int mi[Kk];
#pragma unroll
        for (int i = 0; i < Kk; ++i) { md[i] = FLT_MAX; mi[i] = 0; }
        float mthr = FLT_MAX;
        for (int t = 0; t < cnt; ++t) {
            float cd = ad[tid][t];
            if (cd < mthr) {
                int ci = ai[tid][t];
#pragma unroll
                for (int u = 0; u < Kk; ++u) {
                    bool  sw = cd < md[u];
                    float od = md[u]; int oi = mi[u];
                    md[u] = sw ? cd : od;  mi[u] = sw ? ci : oi;
                    cd    = sw ? od : cd;  ci    = sw ? oi : ci;
                }
                mthr = md[Kk - 1];
            }
        }
        const int orig = sid[blockIdx.x * 32 + tid];
        const int gq   = b * Nn + orig;
        g_ovf[gq] = (cntRaw > CAP) ? 1 : 0;
#pragma unroll
        for (int i = 0; i < Kk; ++i) g_idx[gq * Kk + i] = sid[mi[i]];
    }
}

// ---------------------------------------------------------------------------
__global__ __launch_bounds__(256) void knn_fix_kernel() {
    const int i = blockIdx.x * 256 + threadIdx.x;
    if (i >= ROWS) return;
    if (!g_ovf[i]) return;
    const int b = i >> 13;
    const float4* __restrict__ pos = g_pos4 + b * Nn;
    float4 me = pos[i & 8191];
    const float qx = me.x, qy = me.y, qz = me.z;
    float dist[Kk]; int nid[Kk];
#pragma unroll
    for (int t = 0; t < Kk; ++t) { dist[t] = FLT_MAX; nid[t] = 0; }
    float thr = FLT_MAX;
    for (int j = 0; j < Nn; ++j) {
        float4 cp = pos[j];
        float d2 = fmaf(-2.0f, fmaf(qz, cp.z, fmaf(qy, cp.y, qx * cp.x)), cp.w);
        if (d2 < thr) {
            float cd = d2; int ci = j;
#pragma unroll
            for (int t = 0; t < Kk; ++t) {
                bool  sw = cd < dist[t];
                float od = dist[t]; int oi = nid[t];
                dist[t] = sw ? cd : od;  nid[t] = sw ? ci : oi;
                cd      = sw ? od : cd;  ci     = sw ? oi : ci;
            }
            thr = dist[Kk - 1];
        }
    }
#pragma unroll
    for (int t = 0; t < Kk; ++t) g_idx[i * Kk + t] = nid[t];
}

// ---------------------------------------------------------------------------
// SGEMM (scalar FFMA, round-8 math) + double-buffered smem: one sync per
// k-tile, global prefetch overlaps the FFMA burst. Bit-identical results.
// ---------------------------------------------------------------------------
__global__ __launch_bounds__(256, 2) void sgemm_kernel(const float* __restrict__ A) {
    __shared__ float As[2][16][128];
    __shared__ float Bs[2][16][128];

    const int tid  = threadIdx.x;
    const int bm0  = blockIdx.y * 128;
    const int bn0  = blockIdx.x * 128;

    const int arow = tid >> 2;
    const int acol = (tid & 3) * 4;
    const int brow = tid >> 5;
    const int bcol = (tid & 31) * 4;

    const int tx = tid & 15, ty = tid >> 4;
    const int c0 = tx * 4, c1 = 64 + tx * 4;
    const int r0 = ty * 4, r1 = 64 + ty * 4;

    float acc[8][8];
#pragma unroll
    for (int i = 0; i < 8; ++i)
#pragma unroll
        for (int j = 0; j < 8; ++j) acc[i][j] = 0.0f;

    const float* Aa0 = A + (size_t)(bm0 + arow)      * Cc + acol;
    const float* Aa1 = A + (size_t)(bm0 + arow + 64) * Cc + acol;
    const float* Bb0 = g_M + (size_t)brow       * Ff + bn0 + bcol;
    const float* Bb1 = g_M + (size_t)(brow + 8) * Ff + bn0 + bcol;

    // preload tile 0 into buffer 0
    {
        float4 a0 = *(const float4*)(Aa0);
        float4 a1 = *(const float4*)(Aa1);
        float4 b0 = *(const float4*)(Bb0);
        float4 b1 = *(const float4*)(Bb1);
        As[0][acol + 0][arow] = a0.x; As[0][acol + 1][arow] = a0.y;
        As[0][acol + 2][arow] = a0.z; As[0][acol + 3][arow] = a0.w;
        As[0][acol + 0][arow + 64] = a1.x; As[0][acol + 1][arow + 64] = a1.y;
        As[0][acol + 2][arow + 64] = a1.z; As[0][acol + 3][arow + 64] = a1.w;
        *(float4*)&Bs[0][brow][bcol]     = b0;
        *(float4*)&Bs[0][brow + 8][bcol] = b1;
    }
    __syncthreads();

    for (int t = 0; t < 16; ++t) {
        const int cur = t & 1;

        float4 na0, na1, nb0, nb1;
        if (t < 15) {
            const int kt = (t + 1) * 16;
            na0 = *(const float4*)(Aa0 + kt);
            na1 = *(const float4*)(Aa1 + kt);
            nb0 = *(const float4*)(Bb0 + (size_t)kt * Ff);
            nb1 = *(const float4*)(Bb1 + (size_t)kt * Ff);
        }

#pragma unroll
        for (int kk = 0; kk < 16; ++kk) {
            float4 af0 = *(const float4*)&As[cur][kk][r0];
            float4 af1 = *(const float4*)&As[cur][kk][r1];
            float4 bf0 = *(const float4*)&Bs[cur][kk][c0];
            float4 bf1 = *(const float4*)&Bs[cur][kk][c1];
            float ar[8] = {af0.x, af0.y, af0.z, af0.w, af1.x, af1.y, af1.z, af1.w};
            float br[8] = {bf0.x, bf0.y, bf0.z, bf0.w, bf1.x, bf1.y, bf1.z, bf1.w};
#pragma unroll
            for (int i = 0; i < 8; ++i)
#pragma unroll
                for (int j = 0; j < 8; ++j)
                    acc[i][j] = fmaf(ar[i], br[j], acc[i][j]);
        }

        if (t < 15) {
            const int nxt = cur ^ 1;
            As[nxt][acol + 0][arow] = na0.x; As[nxt][acol + 1][arow] = na0.y;
            As[nxt][acol + 2][arow] = na0.z; As[nxt][acol + 3][arow] = na0.w;
            As[nxt][acol + 0][arow + 64] = na1.x; As[nxt][acol + 1][arow + 64] = na1.y;
            As[nxt][acol + 2][arow + 64] = na1.z; As[nxt][acol + 3][arow + 64] = na1.w;
            *(float4*)&Bs[nxt][brow][bcol]     = nb0;
            *(float4*)&Bs[nxt][brow + 8][bcol] = nb1;
            __syncthreads();
        }
    }

#pragma unroll
    for (int i = 0; i < 8; ++i) {
        int row = bm0 + ((i < 4) ? (r0 + i) : (r1 + i - 4));
        float4 v0 = make_float4(acc[i][0], acc[i][1], acc[i][2], acc[i][3]);
        float4 v1 = make_float4(acc[i][4], acc[i][5], acc[i][6], acc[i][7]);
        *(float4*)(g_Y + (size_t)row * Ff + bn0 + c0) = v0;
        *(float4*)(g_Y + (size_t)row * Ff + bn0 + c1) = v1;
    }
}

// ---------------------------------------------------------------------------
__global__ __launch_bounds__(256) void gather_max_kernel(const float* __restrict__ bias,
                                                         float* __restrict__ out) {
    const int row  = blockIdx.x * 8 + (threadIdx.x >> 5);
    const int lane = threadIdx.x & 31;
    const int b    = row >> 13;

    const int* ir = g_idx + row * Kk;
    int myn = ir[lane & (Kk - 1)];

    const float* Ybase = g_Y + (size_t)(b << 13) * Ff;

    float4 m0 = make_float4(-FLT_MAX, -FLT_MAX, -FLT_MAX, -FLT_MAX);
    float4 m1 = m0;

#pragma unroll
    for (int j = 0; j < Kk; ++j) {
        int nb = __shfl_sync(0xffffffffu, myn, j);
        const float4* Pr = (const float4*)(Ybase + (size_t)nb * Ff);
        float4 a = Pr[lane];
        float4 c = Pr[lane + 32];
        m0.x = fmaxf(m0.x, a.x); m0.y = fmaxf(m0.y, a.y);
        m0.z = fmaxf(m0.z, a.z); m0.w = fmaxf(m0.w, a.w);
        m1.x = fmaxf(m1.x, c.x); m1.y = fmaxf(m1.y, c.y);
        m1.z = fmaxf(m1.z, c.z); m1.w = fmaxf(m1.w, c.w);
    }

    const float4* Ur = (const float4*)(g_Y + (size_t)row * Ff + Cc);
    float4 u0 = Ur[lane], u1 = Ur[lane + 32];
    const float4* Br = (const float4*)bias;
    float4 bb0 = Br[lane], bb1 = Br[lane + 32];

    float4 v0, v1;
    v0.x = m0.x + u0.x + bb0.x; v0.y = m0.y + u0.y + bb0.y;
    v0.z = m0.z + u0.z + bb0.z; v0.w = m0.w + u0.w + bb0.w;
    v1.x = m1.x + u1.x + bb1.x; v1.y = m1.y + u1.y + bb1.y;
    v1.z = m1.z + u1.z + bb1.z; v1.w = m1.w + u1.w + bb1.w;

    v0.x = fmaxf(v0.x, 0.2f * v0.x); v0.y = fmaxf(v0.y, 0.2f * v0.y);
    v0.z = fmaxf(v0.z, 0.2f * v0.z); v0.w = fmaxf(v0.w, 0.2f * v0.w);
    v1.x = fmaxf(v1.x, 0.2f * v1.x); v1.y = fmaxf(v1.y, 0.2f * v1.y);
    v1.z = fmaxf(v1.z, 0.2f * v1.z); v1.w = fmaxf(v1.w, 0.2f * v1.w);

    float4* Or = (float4*)(out + (size_t)row * Cc);
    Or[lane]      = v0;
    Or[lane + 32] = v1;
}

// ---------------------------------------------------------------------------
extern "C" void kernel_launch(void* const* d_in, const int* in_sizes, int n_in,
                              void* d_out, int out_size) {
    const float* q    = (const float*)d_in[0];   // [4,8192,256]
    const float* qpos = (const float*)d_in[1];   // [4,8192,3]
    const float* W    = (const float*)d_in[2];   // [512,256]
    const float* bias = (const float*)d_in[3];   // [256]
    float* out = (float*)d_out;
    (void)in_sizes; (void)n_in; (void)out_size;

    prep_pos_kernel<<<(ROWS + 255) / 256, 256>>>(qpos);
    sort_kernel<<<Bn, 512>>>();
    prep_M_kernel<<<(Cc * Ff + 255) / 256, 256>>>(W);
    knn_kernel<<<dim3(Nn / 32, Bn), 256>>>();
    knn_fix_kernel<<<ROWS / 256, 256>>>();
    sgemm_kernel<<<dim3(Ff / 128, ROWS / 128), 256>>>(q);
    gather_max_kernel<<<ROWS / 8, 256>>>(bias, out);
}

// round 12
// speedup vs baseline: 1.6757x; 1.2017x over previous
#include <cuda_runtime.h>
#include <cuda_bf16.h>
#include <float.h>
#include <stdint.h>

#define Bn   4
#define Nn   8192
#define Cc   256
#define Kk   16
#define Ff   512
#define ROWS (Bn*Nn)
#define CAP  128

__device__ float4 g_pos4 [ROWS];
__device__ float4 g_pos4s[ROWS];
__device__ int    g_sid  [ROWS];
__device__ int    g_ovf  [ROWS];
__device__ float  g_Y[(size_t)ROWS * Ff];
__device__ int    g_idx[ROWS * Kk];
__device__ __nv_bfloat16 g_Ah[(size_t)ROWS * Cc];
__device__ __nv_bfloat16 g_Al[(size_t)ROWS * Cc];
__device__ __nv_bfloat16 g_Bh[Ff * Cc];   // B^T: [n][k]
__device__ __nv_bfloat16 g_Bl[Ff * Cc];

__device__ __forceinline__ uint32_t smem_u32(const void* p) {
    uint32_t a;
    asm("{ .reg .u64 t; cvta.to.shared.u64 t, %1; cvt.u32.u64 %0, t; }" : "=r"(a) : "l"(p));
    return a;
}
#define LDSM_X4(r, addr) \
    asm volatile("ldmatrix.sync.aligned.m8n8.x4.shared.b16 {%0,%1,%2,%3}, [%4];" \
        : "=r"((r)[0]), "=r"((r)[1]), "=r"((r)[2]), "=r"((r)[3]) : "r"(addr))
#define LDSM_X2(r, addr) \
    asm volatile("ldmatrix.sync.aligned.m8n8.x2.shared.b16 {%0,%1}, [%2];" \
        : "=r"((r)[0]), "=r"((r)[1]) : "r"(addr))
#define MMA_BF16(c, a, b) \
    asm volatile("mma.sync.aligned.m16n8k16.row.col.f32.bf16.bf16.f32 " \
        "{%0,%1,%2,%3}, {%4,%5,%6,%7}, {%8,%9}, {%0,%1,%2,%3};" \
        : "+f"((c)[0]), "+f"((c)[1]), "+f"((c)[2]), "+f"((c)[3]) \
        : "r"((a)[0]), "r"((a)[1]), "r"((a)[2]), "r"((a)[3]), "r"((b)[0]), "r"((b)[1]))

// ---------------------------------------------------------------------------
__global__ void prep_pos_kernel(const float* __restrict__ qpos) {
    int i = blockIdx.x * blockDim.x + threadIdx.x;
    if (i >= ROWS) return;
    float x = qpos[i*3+0], y = qpos[i*3+1], z = qpos[i*3+2];
    float n = fmaf(z, z, fmaf(y, y, x * x));
    g_pos4[i] = make_float4(x, y, z, n);
}

__global__ void prep_A_kernel(const float* __restrict__ q) {
    int i = blockIdx.x * 256 + threadIdx.x;
    if (i >= ROWS * Cc / 4) return;
    float4 v = ((const float4*)q)[i];
    __nv_bfloat16 h0 = __float2bfloat16(v.x), h1 = __float2bfloat16(v.y);
    __nv_bfloat16 h2 = __float2bfloat16(v.z), h3 = __float2bfloat16(v.w);
    __nv_bfloat16 l0 = __float2bfloat16(v.x - __bfloat162float(h0));
    __nv_bfloat16 l1 = __float2bfloat16(v.y - __bfloat162float(h1));
    __nv_bfloat16 l2 = __float2bfloat16(v.z - __bfloat162float(h2));
    __nv_bfloat16 l3 = __float2bfloat16(v.w - __bfloat162float(h3));
    uint2 hh, ll;
    hh.x = ((uint32_t)__bfloat16_as_ushort(h1) << 16) | __bfloat16_as_ushort(h0);
    hh.y = ((uint32_t)__bfloat16_as_ushort(h3) << 16) | __bfloat16_as_ushort(h2);
    ll.x = ((uint32_t)__bfloat16_as_ushort(l1) << 16) | __bfloat16_as_ushort(l0);
    ll.y = ((uint32_t)__bfloat16_as_ushort(l3) << 16) | __bfloat16_as_ushort(l2);
    ((uint2*)g_Ah)[i] = hh;
    ((uint2*)g_Al)[i] = ll;
}

__global__ void prep_B_kernel(const float* __restrict__ W) {
    int i = blockIdx.x * 256 + threadIdx.x;
    if (i >= Ff * Cc) return;
    int n = i >> 8;
    int k = i & 255;
    float v;
    if (n < Cc) v = W[k * Cc + n];
    else        v = W[(Cc + k) * Cc + (n - Cc)] - W[k * Cc + (n - Cc)];
    __nv_bfloat16 h = __float2bfloat16(v);
    __nv_bfloat16 l = __float2bfloat16(v - __bfloat162float(h));
    g_Bh[i] = h;
    g_Bl[i] = l;
}

// ---------------------------------------------------------------------------
__global__ __launch_bounds__(512) void sort_kernel() {
    const int b   = blockIdx.x;
    const int tid = threadIdx.x;
    __shared__ unsigned sk[Nn];

    for (int i = tid; i < Nn; i += 512) {
        unsigned u = __float_as_uint(g_pos4[b*Nn + i].x);
        u = (u & 0x80000000u) ? ~u : (u | 0x80000000u);
        sk[i] = (u & 0xFFFFE000u) | (unsigned)i;
    }
    __syncthreads();

    for (int k = 2; k <= Nn; k <<= 1) {
        for (int j = k >> 1; j > 0; j >>= 1) {
            for (int t = tid; t < Nn/2; t += 512) {
                int i   = 2*t - (t & (j - 1));
                int ixj = i + j;
                unsigned a = sk[i], c = sk[ixj];
                bool asc = ((i & k) == 0);
                if ((a > c) == asc) { sk[i] = c; sk[ixj] = a; }
            }
            __syncthreads();
        }
    }

    for (int i = tid; i < Nn; i += 512) {
        int orig = (int)(sk[i] & 8191u);
        g_pos4s[b*Nn + i] = g_pos4[b*Nn + orig];
        g_sid  [b*Nn + i] = orig;
    }
}

// ---------------------------------------------------------------------------
// KNN v3 (round-8, unchanged)
// ---------------------------------------------------------------------------
__global__ __launch_bounds__(256) void knn_kernel() {
    const int b    = blockIdx.y;
    const int tid  = threadIdx.x;
    const int w    = tid >> 5;
    const int lane = tid & 31;
    const int qb   = blockIdx.x * 32 + w * 4;

    const float4* __restrict__ pos = g_pos4s + b * Nn;
    const int*    __restrict__ sid = g_sid   + b * Nn;

    __shared__ float4         tile[1024];
    __shared__ float          ad[32][CAP];
    __shared__ unsigned short ai[32][CAP];
    __shared__ int            acnt[32];

    float qx[4], qy[4], qz[4];
#pragma unroll
    for (int i = 0; i < 4; ++i) {
        float4 m = pos[qb + i];
        qx[i] = m.x; qy[i] = m.y; qz[i] = m.z;
    }

    const int ctile = blockIdx.x >> 5;

    if (tid < 32) acnt[tid] = 0;
    {
        const int t0 = ctile * 1024;
#pragma unroll
        for (int j = 0; j < 4; ++j)
            tile[tid + j * 256] = pos[t0 + tid + j * 256];
    }
    __syncthreads();

    float t1[4], t2[4];
#pragma unroll
    for (int i = 0; i < 4; ++i) { t1[i] = FLT_MAX; t2[i] = FLT_MAX; }

    for (int m = 0; m < 32; m += 4) {
        float4 c0 = tile[lane + (m + 0) * 32];
        float4 c1 = tile[lane + (m + 1) * 32];
        float4 c2 = tile[lane + (m + 2) * 32];
        float4 c3 = tile[lane + (m + 3) * 32];
#pragma unroll
        for (int i = 0; i < 4; ++i) {
            float d0 = fmaf(-2.0f, fmaf(qz[i], c0.z, fmaf(qy[i], c0.y, qx[i] * c0.x)), c0.w);
            float d1 = fmaf(-2.0f, fmaf(qz[i], c1.z, fmaf(qy[i], c1.y, qx[i] * c1.x)), c1.w);
            float d2 = fmaf(-2.0f, fmaf(qz[i], c2.z, fmaf(qy[i], c2.y, qx[i] * c2.x)), c2.w);
            float d3 = fmaf(-2.0f, fmaf(qz[i], c3.z, fmaf(qy[i], c3.y, qx[i] * c3.x)), c3.w);
            float mn01 = fminf(d0, d1), mx01 = fmaxf(d0, d1);
            float mn23 = fminf(d2, d3), mx23 = fmaxf(d2, d3);
            float s1 = fminf(mn01, mn23);
            float s2 = fminf(fmaxf(mn01, mn23), fminf(mx01, mx23));
            float nt1 = fminf(t1[i], s1);
            t2[i] = fminf(fmaxf(t1[i], s1), fminf(t2[i], s2));
            t1[i] = nt1;
        }
    }

    float thr[4];
#pragma unroll
    for (int i = 0; i < 4; ++i) {
        float a = t1[i], bb = t2[i];
        float m = FLT_MAX;
        for (int r = 0; r < 16; ++r) {
            float lo = fminf(a, bb);
            m = lo;
            m = fminf(m, __shfl_xor_sync(0xffffffffu, m, 1));
            m = fminf(m, __shfl_xor_sync(0xffffffffu, m, 2));
            m = fminf(m, __shfl_xor_sync(0xffffffffu, m, 4));
            m = fminf(m, __shfl_xor_sync(0xffffffffu, m, 8));
            m = fminf(m, __shfl_xor_sync(0xffffffffu, m, 16));
            unsigned msk = __ballot_sync(0xffffffffu, lo == m);
            int leader = __ffs(msk) - 1;
            if (lane == leader) {
                if (a <= bb) a = FLT_MAX; else bb = FLT_MAX;
            }
        }
        thr[i] = m;
    }

    for (int ot = 0; ot < 8; ++ot) {
        const int tt = (ctile + ot) & 7;
        const int t0 = tt * 1024;
        if (ot > 0) {
            __syncthreads();
#pragma unroll
            for (int j = 0; j < 4; ++j)
                tile[tid + j * 256] = pos[t0 + tid + j * 256];
            __syncthreads();
        }
        for (int m = 0; m < 32; m += 4) {
            float4 c0 = tile[lane + (m + 0) * 32];
            float4 c1 = tile[lane + (m + 1) * 32];
            float4 c2 = tile[lane + (m + 2) * 32];
            float4 c3 = tile[lane + (m + 3) * 32];
#pragma unroll
            for (int i = 0; i < 4; ++i) {
                float d0 = fmaf(-2.0f, fmaf(qz[i], c0.z, fmaf(qy[i], c0.y, qx[i] * c0.x)), c0.w);
                float d1 = fmaf(-2.0f, fmaf(qz[i], c1.z, fmaf(qy[i], c1.y, qx[i] * c1.x)), c1.w);
                float d2 = fmaf(-2.0f, fmaf(qz[i], c2.z, fmaf(qy[i], c2.y, qx[i] * c2.x)), c2.w);
                float d3 = fmaf(-2.0f, fmaf(qz[i], c3.z, fmaf(qy[i], c3.y, qx[i] * c3.x)), c3.w);
                float mn = fminf(fminf(d0, d1), fminf(d2, d3));
                if (mn <= thr[i]) {
                    const int ql = w * 4 + i;
                    const int jb = t0 + lane + m * 32;
                    if (d0 <= thr[i]) {
                        int sl = atomicAdd(&acnt[ql], 1);
                        if (sl < CAP) { ad[ql][sl] = d0; ai[ql][sl] = (unsigned short)(jb); }
                    }
                    if (d1 <= thr[i]) {
                        int sl = atomicAdd(&acnt[ql], 1);
                        if (sl < CAP) { ad[ql][sl] = d1; ai[ql][sl] = (unsigned short)(jb + 32); }
                    }
                    if (d2 <= thr[i]) {
                        int sl = atomicAdd(&acnt[ql], 1);
                        if (sl < CAP) { ad[ql][sl] = d2; ai[ql][sl] = (unsigned short)(jb + 64); }
                    }
                    if (d3 <= thr[i]) {
                        int sl = atomicAdd(&acnt[ql], 1);
                        if (sl < CAP) { ad[ql][sl] = d3; ai[ql][sl] = (unsigned short)(jb + 96); }
                    }
                }
            }
        }
    }
    __syncthreads();

    if (tid < 32) {
        const int cntRaw = acnt[tid];
        const int cnt    = cntRaw < CAP ? cntRaw : CAP;
        float md[Kk]; int mi[Kk];
#pragma unroll
        for (int i = 0; i < Kk; ++i) { md[i] = FLT_MAX; mi[i] = 0; }
        float mthr = FLT_MAX;
        for (int t = 0; t < cnt; ++t) {
            float cd = ad[tid][t];
            if (cd < mthr) {
                int ci = ai[tid][t];
#pragma unroll
                for (int u = 0; u < Kk; ++u) {
                    bool  sw = cd < md[u];
                    float od = md[u]; int oi = mi[u];
                    md[u] = sw ? cd : od;  mi[u] = sw ? ci : oi;
                    cd    = sw ? od : cd;  ci    = sw ? oi : ci;
                }
                mthr = md[Kk - 1];
            }
        }
        const int orig = sid[blockIdx.x * 32 + tid];
        const int gq   = b * Nn + orig;
        g_ovf[gq] = (cntRaw > CAP) ? 1 : 0;
#pragma unroll
        for (int i = 0; i < Kk; ++i) g_idx[gq * Kk + i] = sid[mi[i]];
    }
}

// ---------------------------------------------------------------------------
__global__ __launch_bounds__(256) void knn_fix_kernel() {
    const int i = blockIdx.x * 256 + threadIdx.x;
    if (i >= ROWS) return;
    if (!g_ovf[i]) return;
    const int b = i >> 13;
    const float4* __restrict__ pos = g_pos4 + b * Nn;
    float4 me = pos[i & 8191];
    const float qx = me.x, qy = me.y, qz = me.z;
    float dist[Kk]; int nid[Kk];
#pragma unroll
    for (int t = 0; t < Kk; ++t) { dist[t] = FLT_MAX; nid[t] = 0; }
    float thr = FLT_MAX;
    for (int j = 0; j < Nn; ++j) {
        float4 cp = pos[j];
        float d2 = fmaf(-2.0f, fmaf(qz, cp.z, fmaf(qy, cp.y, qx * cp.x)), cp.w);
        if (d2 < thr) {
            float cd = d2; int ci = j;
#pragma unroll
            for (int t = 0; t < Kk; ++t) {
                bool  sw = cd < dist[t];
                float od = dist[t]; int oi = nid[t];
                dist[t] = sw ? cd : od;  nid[t] = sw ? ci : oi;
                cd      = sw ? od : cd;  ci     = sw ? oi : ci;
            }
            thr = dist[Kk - 1];
        }
    }
#pragma unroll
    for (int t = 0; t < Kk; ++t) g_idx[i * Kk + t] = nid[t];
}

// ---------------------------------------------------------------------------
// bf16-split GEMM via warp-level mma.sync (HMMA):
// Y = Ah@Bh^T + Ah@Bl^T + Al@Bh^T, fp32 accum.
// 128x128 block tile, 8 warps (2m x 4n), warp tile 64x32, BK=32.
// smem rows padded to 40 bf16 (80B stride) -> conflict-free ldmatrix.
// ---------------------------------------------------------------------------
__global__ __launch_bounds__(256) void gemm_mma_kernel() {
    __shared__ __nv_bfloat16 sAh[128][40];
    __shared__ __nv_bfloat16 sAl[128][40];
    __shared__ __nv_bfloat16 sBh[128][40];
    __shared__ __nv_bfloat16 sBl[128][40];

    const int tid  = threadIdx.x;
    const int wid  = tid >> 5;
    const int lane = tid & 31;
    const int wm   = wid >> 2;          // 0..1
    const int wn   = wid & 3;           // 0..3
    const int bm0  = blockIdx.x * 128;
    const int bn0  = blockIdx.y * 128;

    float acc[4][4][4];
#pragma unroll
    for (int mt = 0; mt < 4; ++mt)
#pragma unroll
        for (int nt = 0; nt < 4; ++nt)
#pragma unroll
            for (int i = 0; i < 4; ++i) acc[mt][nt][i] = 0.0f;

    // frag address precompute
    const int a_sub = lane >> 3, a_r = lane & 7;
    const int a_row_off = (a_sub & 1) * 8 + a_r;
    const int a_col_off = (a_sub >> 1) * 8;
    const int b_sub = (lane >> 3) & 1, b_r = lane & 7;

    for (int kt = 0; kt < 8; ++kt) {
        const int k0 = kt * 32;
#pragma unroll
        for (int half = 0; half < 2; ++half) {
            const int gi  = tid + half * 256;
            const int row = gi >> 2;
            const int g   = gi & 3;
            const size_t aoff = (size_t)(bm0 + row) * Cc + k0 + g * 8;
            const size_t boff = (size_t)(bn0 + row) * Cc + k0 + g * 8;
            *(uint4*)&sAh[row][g * 8] = *(const uint4*)(g_Ah + aoff);
            *(uint4*)&sAl[row][g * 8] = *(const uint4*)(g_Al + aoff);
            *(uint4*)&sBh[row][g * 8] = *(const uint4*)(g_Bh + boff);
            *(uint4*)&sBl[row][g * 8] = *(const uint4*)(g_Bl + boff);
        }
        __syncthreads();

#pragma unroll
        for (int kh = 0; kh < 32; kh += 16) {
            uint32_t ah[4][4], al[4][4], bh[4][2], bl[4][2];
#pragma unroll
            for (int mt = 0; mt < 4; ++mt) {
                const int arow = wm * 64 + mt * 16 + a_row_off;
                const int acol = kh + a_col_off;
                LDSM_X4(ah[mt], smem_u32(&sAh[arow][acol]));
                LDSM_X4(al[mt], smem_u32(&sAl[arow][acol]));
            }
#pragma unroll
            for (int nt = 0; nt < 4; ++nt) {
                const int brow = wn * 32 + nt * 8 + b_r;
                const int bcol = kh + b_sub * 8;
                LDSM_X2(bh[nt], smem_u32(&sBh[brow][bcol]));
                LDSM_X2(bl[nt], smem_u32(&sBl[brow][bcol]));
            }
#pragma unroll
            for (int mt = 0; mt < 4; ++mt)
#pragma unroll
                for (int nt = 0; nt < 4; ++nt) {
                    MMA_BF16(acc[mt][nt], ah[mt], bh[nt]);
                    MMA_BF16(acc[mt][nt], ah[mt], bl[nt]);
                    MMA_BF16(acc[mt][nt], al[mt], bh[nt]);
                }
        }
        __syncthreads();
    }

    const int g   = lane >> 2;
    const int tig = lane & 3;
#pragma unroll
    for (int mt = 0; mt < 4; ++mt)
#pragma unroll
        for (int nt = 0; nt < 4; ++nt) {
            const int row = bm0 + wm * 64 + mt * 16 + g;
            const int col = bn0 + wn * 32 + nt * 8 + tig * 2;
            float2 v0 = make_float2(acc[mt][nt][0], acc[mt][nt][1]);
            float2 v1 = make_float2(acc[mt][nt][2], acc[mt][nt][3]);
            *(float2*)(g_Y + (size_t)row * Ff + col)       = v0;
            *(float2*)(g_Y + (size_t)(row + 8) * Ff + col) = v1;
        }
}

// ---------------------------------------------------------------------------
__global__ __launch_bounds__(256) void gather_max_kernel(const float* __restrict__ bias,
                                                         float* __restrict__ out) {
    const int row  = blockIdx.x * 8 + (threadIdx.x >> 5);
    const int lane = threadIdx.x & 31;
    const int b    = row >> 13;

    const int* ir = g_idx + row * Kk;
    int myn = ir[lane & (Kk - 1)];

    const float* Ybase = g_Y + (size_t)(b << 13) * Ff;

    float4 m0 = make_float4(-FLT_MAX, -FLT_MAX, -FLT_MAX, -FLT_MAX);
    float4 m1 = m0;

#pragma unroll
    for (int j = 0; j < Kk; ++j) {
        int nb = __shfl_sync(0xffffffffu, myn, j);
        const float4* Pr = (const float4*)(Ybase + (size_t)nb * Ff);
        float4 a = Pr[lane];
        float4 c = Pr[lane + 32];
        m0.x = fmaxf(m0.x, a.x); m0.y = fmaxf(m0.y, a.y);
        m0.z = fmaxf(m0.z, a.z); m0.w = fmaxf(m0.w, a.w);
        m1.x = fmaxf(m1.x, c.x); m1.y = fmaxf(m1.y, c.y);
        m1.z = fmaxf(m1.z, c.z); m1.w = fmaxf(m1.w, c.w);
    }

    const float4* Ur = (const float4*)(g_Y + (size_t)row * Ff + Cc);
    float4 u0 = Ur[lane], u1 = Ur[lane + 32];
    const float4* Br = (const float4*)bias;
    float4 bb0 = Br[lane], bb1 = Br[lane + 32];

    float4 v0, v1;
    v0.x = m0.x + u0.x + bb0.x; v0.y = m0.y + u0.y + bb0.y;
    v0.z = m0.z + u0.z + bb0.z; v0.w = m0.w + u0.w + bb0.w;
    v1.x = m1.x + u1.x + bb1.x; v1.y = m1.y + u1.y + bb1.y;
    v1.z = m1.z + u1.z + bb1.z; v1.w = m1.w + u1.w + bb1.w;

    v0.x = fmaxf(v0.x, 0.2f * v0.x); v0.y = fmaxf(v0.y, 0.2f * v0.y);
    v0.z = fmaxf(v0.z, 0.2f * v0.z); v0.w = fmaxf(v0.w, 0.2f * v0.w);
    v1.x = fmaxf(v1.x, 0.2f * v1.x); v1.y = fmaxf(v1.y, 0.2f * v1.y);
    v1.z = fmaxf(v1.z, 0.2f * v1.z); v1.w = fmaxf(v1.w, 0.2f * v1.w);

    float4* Or = (float4*)(out + (size_t)row * Cc);
    Or[lane]      = v0;
    Or[lane + 32] = v1;
}

// ---------------------------------------------------------------------------
extern "C" void kernel_launch(void* const* d_in, const int* in_sizes, int n_in,
                              void* d_out, int out_size) {
    const float* q    = (const float*)d_in[0];   // [4,8192,256]
    const float* qpos = (const float*)d_in[1];   // [4,8192,3]
    const float* W    = (const float*)d_in[2];   // [512,256]
    const float* bias = (const float*)d_in[3];   // [256]
    float* out = (float*)d_out;
    (void)in_sizes; (void)n_in; (void)out_size;

    prep_pos_kernel<<<(ROWS + 255) / 256, 256>>>(qpos);
    sort_kernel<<<Bn, 512>>>();
    prep_A_kernel<<<(ROWS * Cc / 4 + 255) / 256, 256>>>(q);
    prep_B_kernel<<<(Ff * Cc + 255) / 256, 256>>>(W);
    knn_kernel<<<dim3(Nn / 32, Bn), 256>>>();
    knn_fix_kernel<<<ROWS / 256, 256>>>();
    gemm_mma_kernel<<<dim3(ROWS / 128, Ff / 128), 256>>>();
    gather_max_kernel<<<ROWS / 8, 256>>>(bias, out);
}

// round 13
// speedup vs baseline: 1.7733x; 1.0582x over previous
#include <cuda_runtime.h>
#include <cuda_bf16.h>
#include <float.h>
#include <stdint.h>

#define Bn   4
#define Nn   8192
#define Cc   256
#define Kk   16
#define Ff   512
#define ROWS (Bn*Nn)
#define CAP  128

__device__ float4 g_pos4 [ROWS];
__device__ float4 g_pos4s[ROWS];
__device__ int    g_sid  [ROWS];
__device__ int    g_ovf  [ROWS];
__device__ float  g_Y[(size_t)ROWS * Ff];
__device__ int    g_idx[ROWS * Kk];
__device__ __nv_bfloat16 g_Ah[(size_t)ROWS * Cc];
__device__ __nv_bfloat16 g_Al[(size_t)ROWS * Cc];
__device__ __nv_bfloat16 g_Bh[Ff * Cc];   // B^T: [n][k]
__device__ __nv_bfloat16 g_Bl[Ff * Cc];

__device__ __forceinline__ uint32_t smem_u32(const void* p) {
    uint32_t a;
    asm("{ .reg .u64 t; cvta.to.shared.u64 t, %1; cvt.u32.u64 %0, t; }" : "=r"(a) : "l"(p));
    return a;
}
#define LDSM_X4(r, addr) \
    asm volatile("ldmatrix.sync.aligned.m8n8.x4.shared.b16 {%0,%1,%2,%3}, [%4];" \
        : "=r"((r)[0]), "=r"((r)[1]), "=r"((r)[2]), "=r"((r)[3]) : "r"(addr))
#define LDSM_X2(r, addr) \
    asm volatile("ldmatrix.sync.aligned.m8n8.x2.shared.b16 {%0,%1}, [%2];" \
        : "=r"((r)[0]), "=r"((r)[1]) : "r"(addr))
#define MMA_BF16(c, a, b) \
    asm volatile("mma.sync.aligned.m16n8k16.row.col.f32.bf16.bf16.f32 " \
        "{%0,%1,%2,%3}, {%4,%5,%6,%7}, {%8,%9}, {%0,%1,%2,%3};" \
        : "+f"((c)[0]), "+f"((c)[1]), "+f"((c)[2]), "+f"((c)[3]) \
        : "r"((a)[0]), "r"((a)[1]), "r"((a)[2]), "r"((a)[3]), "r"((b)[0]), "r"((b)[1]))

// ---------------------------------------------------------------------------
__global__ void prep_pos_kernel(const float* __restrict__ qpos) {
    int i = blockIdx.x * blockDim.x + threadIdx.x;
    if (i >= ROWS) return;
    float x = qpos[i*3+0], y = qpos[i*3+1], z = qpos[i*3+2];
    float n = fmaf(z, z, fmaf(y, y, x * x));
    g_pos4[i] = make_float4(x, y, z, n);
}

__global__ void prep_A_kernel(const float* __restrict__ q) {
    int i = blockIdx.x * 256 + threadIdx.x;
    if (i >= ROWS * Cc / 4) return;
    float4 v = ((const float4*)q)[i];
    __nv_bfloat16 h0 = __float2bfloat16(v.x), h1 = __float2bfloat16(v.y);
    __nv_bfloat16 h2 = __float2bfloat16(v.z), h3 = __float2bfloat16(v.w);
    __nv_bfloat16 l0 = __float2bfloat16(v.x - __bfloat162float(h0));
    __nv_bfloat16 l1 = __float2bfloat16(v.y - __bfloat162float(h1));
    __nv_bfloat16 l2 = __float2bfloat16(v.z - __bfloat162float(h2));
    __nv_bfloat16 l3 = __float2bfloat16(v.w - __bfloat162float(h3));
    uint2 hh, ll;
    hh.x = ((uint32_t)__bfloat16_as_ushort(h1) << 16) | __bfloat16_as_ushort(h0);
    hh.y = ((uint32_t)__bfloat16_as_ushort(h3) << 16) | __bfloat16_as_ushort(h2);
    ll.x = ((uint32_t)__bfloat16_as_ushort(l1) << 16) | __bfloat16_as_ushort(l0);
    ll.y = ((uint32_t)__bfloat16_as_ushort(l3) << 16) | __bfloat16_as_ushort(l2);
    ((uint2*)g_Ah)[i] = hh;
    ((uint2*)g_Al)[i] = ll;
}

__global__ void prep_B_kernel(const float* __restrict__ W) {
    int i = blockIdx.x * 256 + threadIdx.x;
    if (i >= Ff * Cc) return;
    int n = i >> 8;
    int k = i & 255;
    float v;
    if (n < Cc) v = W[k * Cc + n];
    else        v = W[(Cc + k) * Cc + (n - Cc)] - W[k * Cc + (n - Cc)];
    __nv_bfloat16 h = __float2bfloat16(v);
    __nv_bfloat16 l = __float2bfloat16(v - __bfloat162float(h));
    g_Bh[i] = h;
    g_Bl[i] = l;
}

// ---------------------------------------------------------------------------
__global__ __launch_bounds__(512) void sort_kernel() {
    const int b   = blockIdx.x;
    const int tid = threadIdx.x;
    __shared__ unsigned sk[Nn];

    for (int i = tid; i < Nn; i += 512) {
        unsigned u = __float_as_uint(g_pos4[b*Nn + i].x);
        u = (u & 0x80000000u) ? ~u : (u | 0x80000000u);
        sk[i] = (u & 0xFFFFE000u) | (unsigned)i;
    }
    __syncthreads();

    for (int k = 2; k <= Nn; k <<= 1) {
        for (int j = k >> 1; j > 0; j >>= 1) {
            for (int t = tid; t < Nn/2; t += 512) {
                int i   = 2*t - (t & (j - 1));
                int ixj = i + j;
                unsigned a = sk[i], c = sk[ixj];
                bool asc = ((i & k) == 0);
                if ((a > c) == asc) { sk[i] = c; sk[ixj] = a; }
            }
            __syncthreads();
        }
    }

    for (int i = tid; i < Nn; i += 512) {
        int orig = (int)(sk[i] & 8191u);
        g_pos4s[b*Nn + i] = g_pos4[b*Nn + orig];
        g_sid  [b*Nn + i] = orig;
    }
}

// ---------------------------------------------------------------------------
// KNN v4: v3 + block-uniform exact tile pruning.
// Skip tile t if (x-gap from block's query range to tile's x range)^2 >
// max_i(thr_i + |q_i|^2)  — provably excludes no true top-16 member.
// ---------------------------------------------------------------------------
__global__ __launch_bounds__(256) void knn_kernel() {
    const int b    = blockIdx.y;
    const int tid  = threadIdx.x;
    const int w    = tid >> 5;
    const int lane = tid & 31;
    const int qb   = blockIdx.x * 32 + w * 4;

    const float4* __restrict__ pos = g_pos4s + b * Nn;
    const int*    __restrict__ sid = g_sid   + b * Nn;

    __shared__ float4         tile[1024];
    __shared__ float          ad[32][CAP];
    __shared__ unsigned short ai[32][CAP];
    __shared__ int            acnt[32];
    __shared__ float          wthrt[8];      // per-warp max true-threshold

    float qx[4], qy[4], qz[4], qn[4];
#pragma unroll
    for (int i = 0; i < 4; ++i) {
        float4 m = pos[qb + i];
        qx[i] = m.x; qy[i] = m.y; qz[i] = m.z; qn[i] = m.w;
    }

    const int ctile = blockIdx.x >> 5;

    if (tid < 32) acnt[tid] = 0;
    {
        const int t0 = ctile * 1024;
#pragma unroll
        for (int j = 0; j < 4; ++j)
            tile[tid + j * 256] = pos[t0 + tid + j * 256];
    }
    __syncthreads();

    // ---- phase 1: per-lane top-2 per query over own tile ----
    float t1[4], t2[4];
#pragma unroll
    for (int i = 0; i < 4; ++i) { t1[i] = FLT_MAX; t2[i] = FLT_MAX; }

    for (int m = 0; m < 32; m += 4) {
        float4 c0 = tile[lane + (m + 0) * 32];
        float4 c1 = tile[lane + (m + 1) * 32];
        float4 c2 = tile[lane + (m + 2) * 32];
        float4 c3 = tile[lane + (m + 3) * 32];
#pragma unroll
        for (int i = 0; i < 4; ++i) {
            float d0 = fmaf(-2.0f, fmaf(qz[i], c0.z, fmaf(qy[i], c0.y, qx[i] * c0.x)), c0.w);
            float d1 = fmaf(-2.0f, fmaf(qz[i], c1.z, fmaf(qy[i], c1.y, qx[i] * c1.x)), c1.w);
            float d2 = fmaf(-2.0f, fmaf(qz[i], c2.z, fmaf(qy[i], c2.y, qx[i] * c2.x)), c2.w);
            float d3 = fmaf(-2.0f, fmaf(qz[i], c3.z, fmaf(qy[i], c3.y, qx[i] * c3.x)), c3.w);
            float mn01 = fminf(d0, d1), mx01 = fmaxf(d0, d1);
            float mn23 = fminf(d2, d3), mx23 = fmaxf(d2, d3);
            float s1 = fminf(mn01, mn23);
            float s2 = fminf(fmaxf(mn01, mn23), fminf(mx01, mx23));
            float nt1 = fminf(t1[i], s1);
            t2[i] = fminf(fmaxf(t1[i], s1), fminf(t2[i], s2));
            t1[i] = nt1;
        }
    }

    // warp select-16th of 64-value union => per-query upper bound thr[i]
    float thr[4];
#pragma unroll
    for (int i = 0; i < 4; ++i) {
        float a = t1[i], bb = t2[i];
        float m = FLT_MAX;
        for (int r = 0; r < 16; ++r) {
            float lo = fminf(a, bb);
            m = lo;
            m = fminf(m, __shfl_xor_sync(0xffffffffu, m, 1));
            m = fminf(m, __shfl_xor_sync(0xffffffffu, m, 2));
            m = fminf(m, __shfl_xor_sync(0xffffffffu, m, 4));
            m = fminf(m, __shfl_xor_sync(0xffffffffu, m, 8));
            m = fminf(m, __shfl_xor_sync(0xffffffffu, m, 16));
            unsigned msk = __ballot_sync(0xffffffffu, lo == m);
            int leader = __ffs(msk) - 1;
            if (lane == leader) {
                if (a <= bb) a = FLT_MAX; else bb = FLT_MAX;
            }
        }
        thr[i] = m;
    }

    // block-wide max of true-space thresholds (thr is in d2 - |q|^2 space)
    {
        float wt = fmaxf(fmaxf(thr[0] + qn[0], thr[1] + qn[1]),
                         fmaxf(thr[2] + qn[2], thr[3] + qn[3]));
        if (lane == 0) wthrt[w] = wt;
    }
    __syncthreads();
    float maxthr_true = wthrt[0];
#pragma unroll
    for (int i = 1; i < 8; ++i) maxthr_true = fmaxf(maxthr_true, wthrt[i]);

    // block query x-range (queries are x-sorted & consecutive)
    const float bqxlo = pos[blockIdx.x * 32].x;
    const float bqxhi = pos[blockIdx.x * 32 + 31].x;

    // ---- phase 2: thr-gated append over non-skippable tiles ----
    for (int ot = 0; ot < 8; ++ot) {
        const int tt = (ctile + ot) & 7;
        const int t0 = tt * 1024;
        if (ot > 0) {
            // exact skip test (block-uniform)
            float gap = 0.0f;
            if (tt > ctile)      gap = pos[t0].x - bqxhi;          // tile right of block
            else if (tt < ctile) gap = bqxlo - pos[t0 + 1023].x;   // tile left of block
            if (gap > 0.0f && gap * gap > maxthr_true) continue;

            __syncthreads();
#pragma unroll
            for (int j = 0; j < 4; ++j)
                tile[tid + j * 256] = pos[t0 + tid + j * 256];
            __syncthreads();
        }
        for (int m = 0; m < 32; m += 4) {
            float4 c0 = tile[lane + (m + 0) * 32];
            float4 c1 = tile[lane + (m + 1) * 32];
            float4 c2 = tile[lane + (m + 2) * 32];
            float4 c3 = tile[lane + (m + 3) * 32];
#pragma unroll
            for (int i = 0; i < 4; ++i) {
                float d0 = fmaf(-2.0f, fmaf(qz[i], c0.z, fmaf(qy[i], c0.y, qx[i] * c0.x)), c0.w);
                float d1 = fmaf(-2.0f, fmaf(qz[i], c1.z, fmaf(qy[i], c1.y, qx[i] * c1.x)), c1.w);
                float d2 = fmaf(-2.0f, fmaf(qz[i], c2.z, fmaf(qy[i], c2.y, qx[i] * c2.x)), c2.w);
                float d3 = fmaf(-2.0f, fmaf(qz[i], c3.z, fmaf(qy[i], c3.y, qx[i] * c3.x)), c3.w);
                float mn = fminf(fminf(d0, d1), fminf(d2, d3));
                if (mn <= thr[i]) {
                    const int ql = w * 4 + i;
                    const int jb = t0 + lane + m * 32;
                    if (d0 <= thr[i]) {
                        int sl = atomicAdd(&acnt[ql], 1);
                        if (sl < CAP) { ad[ql][sl] = d0; ai[ql][sl] = (unsigned short)(jb); }
                    }
                    if (d1 <= thr[i]) {
                        int sl = atomicAdd(&acnt[ql], 1);
                        if (sl < CAP) { ad[ql][sl] = d1; ai[ql][sl] = (unsigned short)(jb + 32); }
                    }
                    if (d2 <= thr[i]) {
                        int sl = atomicAdd(&acnt[ql], 1);
                        if (sl < CAP) { ad[ql][sl] = d2; ai[ql][sl] = (unsigned short)(jb + 64); }
                    }
                    if (d3 <= thr[i]) {
                        int sl = atomicAdd(&acnt[ql], 1);
                        if (sl < CAP) { ad[ql][sl] = d3; ai[ql][sl] = (unsigned short)(jb + 96); }
                    }
                }
            }
        }
    }
    __syncthreads();

    if (tid < 32) {
        const int cntRaw = acnt[tid];
        const int cnt    = cntRaw < CAP ? cntRaw : CAP;
        float md[Kk]; int mi[Kk];
#pragma unroll
        for (int i = 0; i < Kk; ++i) { md[i] = FLT_MAX; mi[i] = 0; }
        float mthr = FLT_MAX;
        for (int t = 0; t < cnt; ++t) {
            float cd = ad[tid][t];
            if (cd < mthr) {
                int ci = ai[tid][t];
#pragma unroll
                for (int u = 0; u < Kk; ++u) {
                    bool  sw = cd < md[u];
                    float od = md[u]; int oi = mi[u];
                    md[u] = sw ? cd : od;  mi[u] = sw ? ci : oi;
                    cd    = sw ? od : cd;  ci    = sw ? oi : ci;
                }
                mthr = md[Kk - 1];
            }
        }
        const int orig = sid[blockIdx.x * 32 + tid];
        const int gq   = b * Nn + orig;
        g_ovf[gq] = (cntRaw > CAP) ? 1 : 0;
#pragma unroll
        for (int i = 0; i < Kk; ++i) g_idx[gq * Kk + i] = sid[mi[i]];
    }
}

// ---------------------------------------------------------------------------
__global__ __launch_bounds__(256) void knn_fix_kernel() {
    const int i = blockIdx.x * 256 + threadIdx.x;
    if (i >= ROWS) return;
    if (!g_ovf[i]) return;
    const int b = i >> 13;
    const float4* __restrict__ pos = g_pos4 + b * Nn;
    float4 me = pos[i & 8191];
    const float qx = me.x, qy = me.y, qz = me.z;
    float dist[Kk]; int nid[Kk];
#pragma unroll
    for (int t = 0; t < Kk; ++t) { dist[t] = FLT_MAX; nid[t] = 0; }
    float thr = FLT_MAX;
    for (int j = 0; j < Nn; ++j) {
        float4 cp = pos[j];
        float d2 = fmaf(-2.0f, fmaf(qz, cp.z, fmaf(qy, cp.y, qx * cp.x)), cp.w);
        if (d2 < thr) {
            float cd = d2; int ci = j;
#pragma unroll
            for (int t = 0; t < Kk; ++t) {
                bool  sw = cd < dist[t];
                float od = dist[t]; int oi = nid[t];
                dist[t] = sw ? cd : od;  nid[t] = sw ? ci : oi;
                cd      = sw ? od : cd;  ci     = sw ? oi : ci;
            }
            thr = dist[Kk - 1];
        }
    }
#pragma unroll
    for (int t = 0; t < Kk; ++t) g_idx[i * Kk + t] = nid[t];
}

// ---------------------------------------------------------------------------
// bf16-split GEMM via warp-level mma.sync (HMMA) — round-12, unchanged.
// ---------------------------------------------------------------------------
__global__ __launch_bounds__(256) void gemm_mma_kernel() {
    __shared__ __nv_bfloat16 sAh[128][40];
    __shared__ __nv_bfloat16 sAl[128][40];
    __shared__ __nv_bfloat16 sBh[128][40];
    __shared__ __nv_bfloat16 sBl[128][40];

    const int tid  = threadIdx.x;
    const int wid  = tid >> 5;
    const int lane = tid & 31;
    const int wm   = wid >> 2;
    const int wn   = wid & 3;
    const int bm0  = blockIdx.x * 128;
    const int bn0  = blockIdx.y * 128;

    float acc[4][4][4];
#pragma unroll
    for (int mt = 0; mt < 4; ++mt)
#pragma unroll
        for (int nt = 0; nt < 4; ++nt)
#pragma unroll
            for (int i = 0; i < 4; ++i) acc[mt][nt][i] = 0.0f;

    const int a_sub = lane >> 3, a_r = lane & 7;
    const int a_row_off = (a_sub & 1) * 8 + a_r;
    const int a_col_off = (a_sub >> 1) * 8;
    const int b_sub = (lane >> 3) & 1, b_r = lane & 7;

    for (int kt = 0; kt < 8; ++kt) {
        const int k0 = kt * 32;
#pragma unroll
        for (int half = 0; half < 2; ++half) {
            const int gi  = tid + half * 256;
            const int row = gi >> 2;
            const int g   = gi & 3;
            const size_t aoff = (size_t)(bm0 + row) * Cc + k0 + g * 8;
            const size_t boff = (size_t)(bn0 + row) * Cc + k0 + g * 8;
            *(uint4*)&sAh[row][g * 8] = *(const uint4*)(g_Ah + aoff);
            *(uint4*)&sAl[row][g * 8] = *(const uint4*)(g_Al + aoff);
            *(uint4*)&sBh[row][g * 8] = *(const uint4*)(g_Bh + boff);
            *(uint4*)&sBl[row][g * 8] = *(const uint4*)(g_Bl + boff);
        }
        __syncthreads();

#pragma unroll
        for (int kh = 0; kh < 32; kh += 16) {
            uint32_t ah[4][4], al[4][4], bh[4][2], bl[4][2];
#pragma unroll
            for (int mt = 0; mt < 4; ++mt) {
                const int arow = wm * 64 + mt * 16 + a_row_off;
                const int acol = kh + a_col_off;
                LDSM_X4(ah[mt], smem_u32(&sAh[arow][acol]));
                LDSM_X4(al[mt], smem_u32(&sAl[arow][acol]));
            }
#pragma unroll
            for (int nt = 0; nt < 4; ++nt) {
                const int brow = wn * 32 + nt * 8 + b_r;
                const int bcol = kh + b_sub * 8;
                LDSM_X2(bh[nt], smem_u32(&sBh[brow][bcol]));
                LDSM_X2(bl[nt], smem_u32(&sBl[brow][bcol]));
            }
#pragma unroll
            for (int mt = 0; mt < 4; ++mt)
#pragma unroll
                for (int nt = 0; nt < 4; ++nt) {
                    MMA_BF16(acc[mt][nt], ah[mt], bh[nt]);
                    MMA_BF16(acc[mt][nt], ah[mt], bl[nt]);
                    MMA_BF16(acc[mt][nt], al[mt], bh[nt]);
                }
        }
        __syncthreads();
    }

    const int g   = lane >> 2;
    const int tig = lane & 3;
#pragma unroll
    for (int mt = 0; mt < 4; ++mt)
#pragma unroll
        for (int nt = 0; nt < 4; ++nt) {
            const int row = bm0 + wm * 64 + mt * 16 + g;
            const int col = bn0 + wn * 32 + nt * 8 + tig * 2;
            float2 v0 = make_float2(acc[mt][nt][0], acc[mt][nt][1]);
            float2 v1 = make_float2(acc[mt][nt][2], acc[mt][nt][3]);
            *(float2*)(g_Y + (size_t)row * Ff + col)       = v0;
            *(float2*)(g_Y + (size_t)(row + 8) * Ff + col) = v1;
        }
}

// ---------------------------------------------------------------------------
__global__ __launch_bounds__(256) void gather_max_kernel(const float* __restrict__ bias,
                                                         float* __restrict__ out) {
    const int row  = blockIdx.x * 8 + (threadIdx.x >> 5);
    const int lane = threadIdx.x & 31;
    const int b    = row >> 13;

    const int* ir = g_idx + row * Kk;
    int myn = ir[lane & (Kk - 1)];

    const float* Ybase = g_Y + (size_t)(b << 13) * Ff;

    float4 m0 = make_float4(-FLT_MAX, -FLT_MAX, -FLT_MAX, -FLT_MAX);
    float4 m1 = m0;

#pragma unroll
    for (int j = 0; j < Kk; ++j) {
        int nb = __shfl_sync(0xffffffffu, myn, j);
        const float4* Pr = (const float4*)(Ybase + (size_t)nb * Ff);
        float4 a = Pr[lane];
        float4 c = Pr[lane + 32];
        m0.x = fmaxf(m0.x, a.x); m0.y = fmaxf(m0.y, a.y);
        m0.z = fmaxf(m0.z, a.z); m0.w = fmaxf(m0.w, a.w);
        m1.x = fmaxf(m1.x, c.x); m1.y = fmaxf(m1.y, c.y);
        m1.z = fmaxf(m1.z, c.z); m1.w = fmaxf(m1.w, c.w);
    }

    const float4* Ur = (const float4*)(g_Y + (size_t)row * Ff + Cc);
    float4 u0 = Ur[lane], u1 = Ur[lane + 32];
    const float4* Br = (const float4*)bias;
    float4 bb0 = Br[lane], bb1 = Br[lane + 32];

    float4 v0, v1;
    v0.x = m0.x + u0.x + bb0.x; v0.y = m0.y + u0.y + bb0.y;
    v0.z = m0.z + u0.z + bb0.z; v0.w = m0.w + u0.w + bb0.w;
    v1.x = m1.x + u1.x + bb1.x; v1.y = m1.y + u1.y + bb1.y;
    v1.z = m1.z + u1.z + bb1.z; v1.w = m1.w + u1.w + bb1.w;

    v0.x = fmaxf(v0.x, 0.2f * v0.x); v0.y = fmaxf(v0.y, 0.2f * v0.y);
    v0.z = fmaxf(v0.z, 0.2f * v0.z); v0.w = fmaxf(v0.w, 0.2f * v0.w);
    v1.x = fmaxf(v1.x, 0.2f * v1.x); v1.y = fmaxf(v1.y, 0.2f * v1.y);
    v1.z = fmaxf(v1.z, 0.2f * v1.z); v1.w = fmaxf(v1.w, 0.2f * v1.w);

    float4* Or = (float4*)(out + (size_t)row * Cc);
    Or[lane]      = v0;
    Or[lane + 32] = v1;
}

// ---------------------------------------------------------------------------
extern "C" void kernel_launch(void* const* d_in, const int* in_sizes, int n_in,
                              void* d_out, int out_size) {
    const float* q    = (const float*)d_in[0];   // [4,8192,256]
    const float* qpos = (const float*)d_in[1];   // [4,8192,3]
    const float* W    = (const float*)d_in[2];   // [512,256]
    const float* bias = (const float*)d_in[3];   // [256]
    float* out = (float*)d_out;
    (void)in_sizes; (void)n_in; (void)out_size;

    prep_pos_kernel<<<(ROWS + 255) / 256, 256>>>(qpos);
    sort_kernel<<<Bn, 512>>>();
    prep_A_kernel<<<(ROWS * Cc / 4 + 255) / 256, 256>>>(q);
    prep_B_kernel<<<(Ff * Cc + 255) / 256, 256>>>(W);
    knn_kernel<<<dim3(Nn / 32, Bn), 256>>>();
    knn_fix_kernel<<<ROWS / 256, 256>>>();
    gemm_mma_kernel<<<dim3(ROWS / 128, Ff / 128), 256>>>();
    gather_max_kernel<<<ROWS / 8, 256>>>(bias, out);
}

// round 14
// speedup vs baseline: 2.0708x; 1.1678x over previous
#include <cuda_runtime.h>
#include <cuda_bf16.h>
#include <float.h>
#include <stdint.h>

#define Bn   4
#define Nn   8192
#define Cc   256
#define Kk   16
#define Ff   512
#define ROWS (Bn*Nn)
#define CAP  128

__device__ float4 g_pos4 [ROWS];
__device__ float4 g_pos4s[ROWS];
__device__ int    g_sid  [ROWS];
__device__ int    g_ovf  [ROWS];
__device__ float  g_Y[(size_t)ROWS * Ff];
__device__ int    g_idx[ROWS * Kk];
__device__ __nv_bfloat16 g_Ah[(size_t)ROWS * Cc];
__device__ __nv_bfloat16 g_Al[(size_t)ROWS * Cc];
__device__ __nv_bfloat16 g_Bh[Ff * Cc];   // B^T: [n][k]
__device__ __nv_bfloat16 g_Bl[Ff * Cc];

__device__ __forceinline__ uint32_t smem_u32(const void* p) {
    uint32_t a;
    asm("{ .reg .u64 t; cvta.to.shared.u64 t, %1; cvt.u32.u64 %0, t; }" : "=r"(a) : "l"(p));
    return a;
}
#define LDSM_X4(r, addr) \
    asm volatile("ldmatrix.sync.aligned.m8n8.x4.shared.b16 {%0,%1,%2,%3}, [%4];" \
        : "=r"((r)[0]), "=r"((r)[1]), "=r"((r)[2]), "=r"((r)[3]) : "r"(addr))
#define LDSM_X2(r, addr) \
    asm volatile("ldmatrix.sync.aligned.m8n8.x2.shared.b16 {%0,%1}, [%2];" \
        : "=r"((r)[0]), "=r"((r)[1]) : "r"(addr))
#define MMA_BF16(c, a, b) \
    asm volatile("mma.sync.aligned.m16n8k16.row.col.f32.bf16.bf16.f32 " \
        "{%0,%1,%2,%3}, {%4,%5,%6,%7}, {%8,%9}, {%0,%1,%2,%3};" \
        : "+f"((c)[0]), "+f"((c)[1]), "+f"((c)[2]), "+f"((c)[3]) \
        : "r"((a)[0]), "r"((a)[1]), "r"((a)[2]), "r"((a)[3]), "r"((b)[0]), "r"((b)[1]))

// ---------------------------------------------------------------------------
__global__ void prep_pos_kernel(const float* __restrict__ qpos) {
    int i = blockIdx.x * blockDim.x + threadIdx.x;
    if (i >= ROWS) return;
    float x = qpos[i*3+0], y = qpos[i*3+1], z = qpos[i*3+2];
    float n = fmaf(z, z, fmaf(y, y, x * x));
    g_pos4[i] = make_float4(x, y, z, n);
}

__global__ void prep_A_kernel(const float* __restrict__ q) {
    int i = blockIdx.x * 256 + threadIdx.x;
    if (i >= ROWS * Cc / 4) return;
    float4 v = ((const float4*)q)[i];
    __nv_bfloat16 h0 = __float2bfloat16(v.x), h1 = __float2bfloat16(v.y);
    __nv_bfloat16 h2 = __float2bfloat16(v.z), h3 = __float2bfloat16(v.w);
    __nv_bfloat16 l0 = __float2bfloat16(v.x - __bfloat162float(h0));
    __nv_bfloat16 l1 = __float2bfloat16(v.y - __bfloat162float(h1));
    __nv_bfloat16 l2 = __float2bfloat16(v.z - __bfloat162float(h2));
    __nv_bfloat16 l3 = __float2bfloat16(v.w - __bfloat162float(h3));
    uint2 hh, ll;
    hh.x = ((uint32_t)__bfloat16_as_ushort(h1) << 16) | __bfloat16_as_ushort(h0);
    hh.y = ((uint32_t)__bfloat16_as_ushort(h3) << 16) | __bfloat16_as_ushort(h2);
    ll.x = ((uint32_t)__bfloat16_as_ushort(l1) << 16) | __bfloat16_as_ushort(l0);
    ll.y = ((uint32_t)__bfloat16_as_ushort(l3) << 16) | __bfloat16_as_ushort(l2);
    ((uint2*)g_Ah)[i] = hh;
    ((uint2*)g_Al)[i] = ll;
}

__global__ void prep_B_kernel(const float* __restrict__ W) {
    int i = blockIdx.x * 256 + threadIdx.x;
    if (i >= Ff * Cc) return;
    int n = i >> 8;
    int k = i & 255;
    float v;
    if (n < Cc) v = W[k * Cc + n];
    else        v = W[(Cc + k) * Cc + (n - Cc)] - W[k * Cc + (n - Cc)];
    __nv_bfloat16 h = __float2bfloat16(v);
    __nv_bfloat16 l = __float2bfloat16(v - __bfloat162float(h));
    g_Bh[i] = h;
    g_Bl[i] = l;
}

// ---------------------------------------------------------------------------
__global__ __launch_bounds__(512) void sort_kernel() {
    const int b   = blockIdx.x;
    const int tid = threadIdx.x;
    __shared__ unsigned sk[Nn];

    for (int i = tid; i < Nn; i += 512) {
        unsigned u = __float_as_uint(g_pos4[b*Nn + i].x);
        u = (u & 0x80000000u) ? ~u : (u | 0x80000000u);
        sk[i] = (u & 0xFFFFE000u) | (unsigned)i;
    }
    __syncthreads();

    for (int k = 2; k <= Nn; k <<= 1) {
        for (int j = k >> 1; j > 0; j >>= 1) {
            for (int t = tid; t < Nn/2; t += 512) {
                int i   = 2*t - (t & (j - 1));
                int ixj = i + j;
                unsigned a = sk[i], c = sk[ixj];
                bool asc = ((i & k) == 0);
                if ((a > c) == asc) { sk[i] = c; sk[ixj] = a; }
            }
            __syncthreads();
        }
    }

    for (int i = tid; i < Nn; i += 512) {
        int orig = (int)(sk[i] & 8191u);
        g_pos4s[b*Nn + i] = g_pos4[b*Nn + orig];
        g_sid  [b*Nn + i] = orig;
    }
}

// ---------------------------------------------------------------------------
// KNN v4 (round-13, unchanged): block-uniform exact tile pruning.
// ---------------------------------------------------------------------------
__global__ __launch_bounds__(256) void knn_kernel() {
    const int b    = blockIdx.y;
    const int tid  = threadIdx.x;
    const int w    = tid >> 5;
    const int lane = tid & 31;
    const int qb   = blockIdx.x * 32 + w * 4;

    const float4* __restrict__ pos = g_pos4s + b * Nn;
    const int*    __restrict__ sid = g_sid   + b * Nn;

    __shared__ float4         tile[1024];
    __shared__ float          ad[32][CAP];
    __shared__ unsigned short ai[32][CAP];
    __shared__ int            acnt[32];
    __shared__ float          wthrt[8];

    float qx[4], qy[4], qz[4], qn[4];
#pragma unroll
    for (int i = 0; i < 4; ++i) {
        float4 m = pos[qb + i];
        qx[i] = m.x; qy[i] = m.y; qz[i] = m.z; qn[i] = m.w;
    }

    const int ctile = blockIdx.x >> 5;

    if (tid < 32) acnt[tid] = 0;
    {
        const int t0 = ctile * 1024;
#pragma unroll
        for (int j = 0; j < 4; ++j)
            tile[tid + j * 256] = pos[t0 + tid + j * 256];
    }
    __syncthreads();

    float t1[4], t2[4];
#pragma unroll
    for (int i = 0; i < 4; ++i) { t1[i] = FLT_MAX; t2[i] = FLT_MAX; }

    for (int m = 0; m < 32; m += 4) {
        float4 c0 = tile[lane + (m + 0) * 32];
        float4 c1 = tile[lane + (m + 1) * 32];
        float4 c2 = tile[lane + (m + 2) * 32];
        float4 c3 = tile[lane + (m + 3) * 32];
#pragma unroll
        for (int i = 0; i < 4; ++i) {
            float d0 = fmaf(-2.0f, fmaf(qz[i], c0.z, fmaf(qy[i], c0.y, qx[i] * c0.x)), c0.w);
            float d1 = fmaf(-2.0f, fmaf(qz[i], c1.z, fmaf(qy[i], c1.y, qx[i] * c1.x)), c1.w);
            float d2 = fmaf(-2.0f, fmaf(qz[i], c2.z, fmaf(qy[i], c2.y, qx[i] * c2.x)), c2.w);
            float d3 = fmaf(-2.0f, fmaf(qz[i], c3.z, fmaf(qy[i], c3.y, qx[i] * c3.x)), c3.w);
            float mn01 = fminf(d0, d1), mx01 = fmaxf(d0, d1);
            float mn23 = fminf(d2, d3), mx23 = fmaxf(d2, d3);
            float s1 = fminf(mn01, mn23);
            float s2 = fminf(fmaxf(mn01, mn23), fminf(mx01, mx23));
            float nt1 = fminf(t1[i], s1);
            t2[i] = fminf(fmaxf(t1[i], s1), fminf(t2[i], s2));
            t1[i] = nt1;
        }
    }

    float thr[4];
#pragma unroll
    for (int i = 0; i < 4; ++i) {
        float a = t1[i], bb = t2[i];
        float m = FLT_MAX;
        for (int r = 0; r < 16; ++r) {
            float lo = fminf(a, bb);
            m = lo;
            m = fminf(m, __shfl_xor_sync(0xffffffffu, m, 1));
            m = fminf(m, __shfl_xor_sync(0xffffffffu, m, 2));
            m = fminf(m, __shfl_xor_sync(0xffffffffu, m, 4));
            m = fminf(m, __shfl_xor_sync(0xffffffffu, m, 8));
            m = fminf(m, __shfl_xor_sync(0xffffffffu, m, 16));
            unsigned msk = __ballot_sync(0xffffffffu, lo == m);
            int leader = __ffs(msk) - 1;
            if (lane == leader) {
                if (a <= bb) a = FLT_MAX; else bb = FLT_MAX;
            }
        }
        thr[i] = m;
    }

    {
        float wt = fmaxf(fmaxf(thr[0] + qn[0], thr[1] + qn[1]),
                         fmaxf(thr[2] + qn[2], thr[3] + qn[3]));
        if (lane == 0) wthrt[w] = wt;
    }
    __syncthreads();
    float maxthr_true = wthrt[0];
#pragma unroll
    for (int i = 1; i < 8; ++i) maxthr_true = fmaxf(maxthr_true, wthrt[i]);

    const float bqxlo = pos[blockIdx.x * 32].x;
    const float bqxhi = pos[blockIdx.x * 32 + 31].x;

    for (int ot = 0; ot < 8; ++ot) {
        const int tt = (ctile + ot) & 7;
        const int t0 = tt * 1024;
        if (ot > 0) {
            float gap = 0.0f;
            if (tt > ctile)      gap = pos[t0].x - bqxhi;
            else if (tt < ctile) gap = bqxlo - pos[t0 + 1023].x;
            if (gap > 0.0f && gap * gap > maxthr_true) continue;

            __syncthreads();
#pragma unroll
            for (int j = 0; j < 4; ++j)
                tile[tid + j * 256] = pos[t0 + tid + j * 256];
            __syncthreads();
        }
        for (int m = 0; m < 32; m += 4) {
            float4 c0 = tile[lane + (m + 0) * 32];
            float4 c1 = tile[lane + (m + 1) * 32];
            float4 c2 = tile[lane + (m + 2) * 32];
            float4 c3 = tile[lane + (m + 3) * 32];
#pragma unroll
            for (int i = 0; i < 4; ++i) {
                float d0 = fmaf(-2.0f, fmaf(qz[i], c0.z, fmaf(qy[i], c0.y, qx[i] * c0.x)), c0.w);
                float d1 = fmaf(-2.0f, fmaf(qz[i], c1.z, fmaf(qy[i], c1.y, qx[i] * c1.x)), c1.w);
                float d2 = fmaf(-2.0f, fmaf(qz[i], c2.z, fmaf(qy[i], c2.y, qx[i] * c2.x)), c2.w);
                float d3 = fmaf(-2.0f, fmaf(qz[i], c3.z, fmaf(qy[i], c3.y, qx[i] * c3.x)), c3.w);
                float mn = fminf(fminf(d0, d1), fminf(d2, d3));
                if (mn <= thr[i]) {
                    const int ql = w * 4 + i;
                    const int jb = t0 + lane + m * 32;
                    if (d0 <= thr[i]) {
                        int sl = atomicAdd(&acnt[ql], 1);
                        if (sl < CAP) { ad[ql][sl] = d0; ai[ql][sl] = (unsigned short)(jb); }
                    }
                    if (d1 <= thr[i]) {
                        int sl = atomicAdd(&acnt[ql], 1);
                        if (sl < CAP) { ad[ql][sl] = d1; ai[ql][sl] = (unsigned short)(jb + 32); }
                    }
                    if (d2 <= thr[i]) {
                        int sl = atomicAdd(&acnt[ql], 1);
                        if (sl < CAP) { ad[ql][sl] = d2; ai[ql][sl] = (unsigned short)(jb + 64); }
                    }
                    if (d3 <= thr[i]) {
                        int sl = atomicAdd(&acnt[ql], 1);
                        if (sl < CAP) { ad[ql][sl] = d3; ai[ql][sl] = (unsigned short)(jb + 96); }
                    }
                }
            }
        }
    }
    __syncthreads();

    if (tid < 32) {
        const int cntRaw = acnt[tid];
        const int cnt    = cntRaw < CAP ? cntRaw : CAP;
        float md[Kk]; int mi[Kk];
#pragma unroll
        for (int i = 0; i < Kk; ++i) { md[i] = FLT_MAX; mi[i] = 0; }
        float mthr = FLT_MAX;
        for (int t = 0; t < cnt; ++t) {
            float cd = ad[tid][t];
            if (cd < mthr) {
                int ci = ai[tid][t];
#pragma unroll
                for (int u = 0; u < Kk; ++u) {
                    bool  sw = cd < md[u];
                    float od = md[u]; int oi = mi[u];
                    md[u] = sw ? cd : od;  mi[u] = sw ? ci : oi;
                    cd    = sw ? od : cd;  ci    = sw ? oi : ci;
                }
                mthr = md[Kk - 1];
            }
        }
        const int orig = sid[blockIdx.x * 32 + tid];
        const int gq   = b * Nn + orig;
        g_ovf[gq] = (cntRaw > CAP) ? 1 : 0;
#pragma unroll
        for (int i = 0; i < Kk; ++i) g_idx[gq * Kk + i] = sid[mi[i]];
    }
}

// ---------------------------------------------------------------------------
__global__ __launch_bounds__(256) void knn_fix_kernel() {
    const int i = blockIdx.x * 256 + threadIdx.x;
    if (i >= ROWS) return;
    if (!g_ovf[i]) return;
    const int b = i >> 13;
    const float4* __restrict__ pos = g_pos4 + b * Nn;
    float4 me = pos[i & 8191];
    const float qx = me.x, qy = me.y, qz = me.z;
    float dist[Kk]; int nid[Kk];
#pragma unroll
    for (int t = 0; t < Kk; ++t) { dist[t] = FLT_MAX; nid[t] = 0; }
    float thr = FLT_MAX;
    for (int j = 0; j < Nn; ++j) {
        float4 cp = pos[j];
        float d2 = fmaf(-2.0f, fmaf(qz, cp.z, fmaf(qy, cp.y, qx * cp.x)), cp.w);
        if (d2 < thr) {
            float cd = d2; int ci = j;
#pragma unroll
            for (int t = 0; t < Kk; ++t) {
                bool  sw = cd < dist[t];
                float od = dist[t]; int oi = nid[t];
                dist[t] = sw ? cd : od;  nid[t] = sw ? ci : oi;
                cd      = sw ? od : cd;  ci     = sw ? oi : ci;
            }
            thr = dist[Kk - 1];
        }
    }
#pragma unroll
    for (int t = 0; t < Kk; ++t) g_idx[i * Kk + t] = nid[t];
}

// ---------------------------------------------------------------------------
// bf16-split GEMM via warp-level mma.sync (HMMA) — round-12, unchanged.
// ---------------------------------------------------------------------------
__global__ __launch_bounds__(256) void gemm_mma_kernel() {
    __shared__ __nv_bfloat16 sAh[128][40];
    __shared__ __nv_bfloat16 sAl[128][40];
    __shared__ __nv_bfloat16 sBh[128][40];
    __shared__ __nv_bfloat16 sBl[128][40];

    const int tid  = threadIdx.x;
    const int wid  = tid >> 5;
    const int lane = tid & 31;
    const int wm   = wid >> 2;
    const int wn   = wid & 3;
    const int bm0  = blockIdx.x * 128;
    const int bn0  = blockIdx.y * 128;

    float acc[4][4][4];
#pragma unroll
    for (int mt = 0; mt < 4; ++mt)
#pragma unroll
        for (int nt = 0; nt < 4; ++nt)
#pragma unroll
            for (int i = 0; i < 4; ++i) acc[mt][nt][i] = 0.0f;

    const int a_sub = lane >> 3, a_r = lane & 7;
    const int a_row_off = (a_sub & 1) * 8 + a_r;
    const int a_col_off = (a_sub >> 1) * 8;
    const int b_sub = (lane >> 3) & 1, b_r = lane & 7;

    for (int kt = 0; kt < 8; ++kt) {
        const int k0 = kt * 32;
#pragma unroll
        for (int half = 0; half < 2; ++half) {
            const int gi  = tid + half * 256;
            const int row = gi >> 2;
            const int g   = gi & 3;
            const size_t aoff = (size_t)(bm0 + row) * Cc + k0 + g * 8;
            const size_t boff = (size_t)(bn0 + row) * Cc + k0 + g * 8;
            *(uint4*)&sAh[row][g * 8] = *(const uint4*)(g_Ah + aoff);
            *(uint4*)&sAl[row][g * 8] = *(const uint4*)(g_Al + aoff);
            *(uint4*)&sBh[row][g * 8] = *(const uint4*)(g_Bh + boff);
            *(uint4*)&sBl[row][g * 8] = *(const uint4*)(g_Bl + boff);
        }
        __syncthreads();

#pragma unroll
        for (int kh = 0; kh < 32; kh += 16) {
            uint32_t ah[4][4], al[4][4], bh[4][2], bl[4][2];
#pragma unroll
            for (int mt = 0; mt < 4; ++mt) {
                const int arow = wm * 64 + mt * 16 + a_row_off;
                const int acol = kh + a_col_off;
                LDSM_X4(ah[mt], smem_u32(&sAh[arow][acol]));
                LDSM_X4(al[mt], smem_u32(&sAl[arow][acol]));
            }
#pragma unroll
            for (int nt = 0; nt < 4; ++nt) {
                const int brow = wn * 32 + nt * 8 + b_r;
                const int bcol = kh + b_sub * 8;
                LDSM_X2(bh[nt], smem_u32(&sBh[brow][bcol]));
                LDSM_X2(bl[nt], smem_u32(&sBl[brow][bcol]));
            }
#pragma unroll
            for (int mt = 0; mt < 4; ++mt)
#pragma unroll
                for (int nt = 0; nt < 4; ++nt) {
                    MMA_BF16(acc[mt][nt], ah[mt], bh[nt]);
                    MMA_BF16(acc[mt][nt], ah[mt], bl[nt]);
                    MMA_BF16(acc[mt][nt], al[mt], bh[nt]);
                }
        }
        __syncthreads();
    }

    const int g   = lane >> 2;
    const int tig = lane & 3;
#pragma unroll
    for (int mt = 0; mt < 4; ++mt)
#pragma unroll
        for (int nt = 0; nt < 4; ++nt) {
            const int row = bm0 + wm * 64 + mt * 16 + g;
            const int col = bn0 + wn * 32 + nt * 8 + tig * 2;
            float2 v0 = make_float2(acc[mt][nt][0], acc[mt][nt][1]);
            float2 v1 = make_float2(acc[mt][nt][2], acc[mt][nt][3]);
            *(float2*)(g_Y + (size_t)row * Ff + col)       = v0;
            *(float2*)(g_Y + (size_t)(row + 8) * Ff + col) = v1;
        }
}

// ---------------------------------------------------------------------------
__global__ __launch_bounds__(256) void gather_max_kernel(const float* __restrict__ bias,
                                                         float* __restrict__ out) {
    const int row  = blockIdx.x * 8 + (threadIdx.x >> 5);
    const int lane = threadIdx.x & 31;
    const int b    = row >> 13;

    const int* ir = g_idx + row * Kk;
    int myn = ir[lane & (Kk - 1)];

    const float* Ybase = g_Y + (size_t)(b << 13) * Ff;

    float4 m0 = make_float4(-FLT_MAX, -FLT_MAX, -FLT_MAX, -FLT_MAX);
    float4 m1 = m0;

#pragma unroll
    for (int j = 0; j < Kk; ++j) {
        int nb = __shfl_sync(0xffffffffu, myn, j);
        const float4* Pr = (const float4*)(Ybase + (size_t)nb * Ff);
        float4 a = Pr[lane];
        float4 c = Pr[lane + 32];
        m0.x = fmaxf(m0.x, a.x); m0.y = fmaxf(m0.y, a.y);
        m0.z = fmaxf(m0.z, a.z); m0.w = fmaxf(m0.w, a.w);
        m1.x = fmaxf(m1.x, c.x); m1.y = fmaxf(m1.y, c.y);
        m1.z = fmaxf(m1.z, c.z); m1.w = fmaxf(m1.w, c.w);
    }

    const float4* Ur = (const float4*)(g_Y + (size_t)row * Ff + Cc);
    float4 u0 = Ur[lane], u1 = Ur[lane + 32];
    const float4* Br = (const float4*)bias;
    float4 bb0 = Br[lane], bb1 = Br[lane + 32];

    float4 v0, v1;
    v0.x = m0.x + u0.x + bb0.x; v0.y = m0.y + u0.y + bb0.y;
    v0.z = m0.z + u0.z + bb0.z; v0.w = m0.w + u0.w + bb0.w;
    v1.x = m1.x + u1.x + bb1.x; v1.y = m1.y + u1.y + bb1.y;
    v1.z = m1.z + u1.z + bb1.z; v1.w = m1.w + u1.w + bb1.w;

    v0.x = fmaxf(v0.x, 0.2f * v0.x); v0.y = fmaxf(v0.y, 0.2f * v0.y);
    v0.z = fmaxf(v0.z, 0.2f * v0.z); v0.w = fmaxf(v0.w, 0.2f * v0.w);
    v1.x = fmaxf(v1.x, 0.2f * v1.x); v1.y = fmaxf(v1.y, 0.2f * v1.y);
    v1.z = fmaxf(v1.z, 0.2f * v1.z); v1.w = fmaxf(v1.w, 0.2f * v1.w);

    float4* Or = (float4*)(out + (size_t)row * Cc);
    Or[lane]      = v0;
    Or[lane + 32] = v1;
}

// ---------------------------------------------------------------------------
extern "C" void kernel_launch(void* const* d_in, const int* in_sizes, int n_in,
                              void* d_out, int out_size) {
    const float* q    = (const float*)d_in[0];   // [4,8192,256]
    const float* qpos = (const float*)d_in[1];   // [4,8192,3]
    const float* W    = (const float*)d_in[2];   // [512,256]
    const float* bias = (const float*)d_in[3];   // [256]
    float* out = (float*)d_out;
    (void)in_sizes; (void)n_in; (void)out_size;

    // Fork the capture: KNN chain on the entry stream, GEMM chain on a side
    // stream. Streams/events created fresh each call (never destroyed here —
    // capture is still active when this function returns; a handful of calls
    // total, no device-memory allocation involved).
    cudaStream_t s2;
    cudaEvent_t eFork, eJoin;
    cudaStreamCreateWithFlags(&s2, cudaStreamNonBlocking);
    cudaEventCreateWithFlags(&eFork, cudaEventDisableTiming);
    cudaEventCreateWithFlags(&eJoin, cudaEventDisableTiming);

    cudaEventRecord(eFork, 0);
    cudaStreamWaitEvent(s2, eFork, 0);

    // --- side branch: GEMM chain ---
    prep_A_kernel<<<(ROWS * Cc / 4 + 255) / 256, 256, 0, s2>>>(q);
    prep_B_kernel<<<(Ff * Cc + 255) / 256, 256, 0, s2>>>(W);
    gemm_mma_kernel<<<dim3(ROWS / 128, Ff / 128), 256, 0, s2>>>();
    cudaEventRecord(eJoin, s2);

    // --- main branch: KNN chain ---
    prep_pos_kernel<<<(ROWS + 255) / 256, 256>>>(qpos);
    sort_kernel<<<Bn, 512>>>();
    knn_kernel<<<dim3(Nn / 32, Bn), 256>>>();
    knn_fix_kernel<<<ROWS / 256, 256>>>();

    // --- join, then epilogue ---
    cudaStreamWaitEvent(0, eJoin, 0);
    gather_max_kernel<<<ROWS / 8, 256>>>(bias, out);
}

// round 15
// speedup vs baseline: 2.1787x; 1.0521x over previous
#include <cuda_runtime.h>
#include <cuda_bf16.h>
#include <cuda_fp16.h>
#include <float.h>
#include <stdint.h>

#define Bn   4
#define Nn   8192
#define Cc   256
#define Kk   16
#define Ff   512
#define ROWS (Bn*Nn)
#define CAP  128

__device__ float4 g_pos4 [ROWS];
__device__ float4 g_pos4s[ROWS];
__device__ int    g_sid  [ROWS];
__device__ int    g_ovf  [ROWS];
__device__ __half g_Ph[(size_t)ROWS * Cc];   // P = q@Wa   (fp16, gather-only)
__device__ float  g_U [(size_t)ROWS * Cc];   // U = q@(Wb-Wa)  (fp32)
__device__ int    g_idx[ROWS * Kk];
__device__ __nv_bfloat16 g_Ah[(size_t)ROWS * Cc];
__device__ __nv_bfloat16 g_Al[(size_t)ROWS * Cc];
__device__ __nv_bfloat16 g_Bh[Ff * Cc];   // B^T: [n][k]
__device__ __nv_bfloat16 g_Bl[Ff * Cc];

__device__ __forceinline__ uint32_t smem_u32(const void* p) {
    uint32_t a;
    asm("{ .reg .u64 t; cvta.to.shared.u64 t, %1; cvt.u32.u64 %0, t; }" : "=r"(a) : "l"(p));
    return a;
}
#define LDSM_X4(r, addr) \
    asm volatile("ldmatrix.sync.aligned.m8n8.x4.shared.b16 {%0,%1,%2,%3}, [%4];" \
        : "=r"((r)[0]), "=r"((r)[1]), "=r"((r)[2]), "=r"((r)[3]) : "r"(addr))
#define LDSM_X2(r, addr) \
    asm volatile("ldmatrix.sync.aligned.m8n8.x2.shared.b16 {%0,%1}, [%2];" \
        : "=r"((r)[0]), "=r"((r)[1]) : "r"(addr))
#define MMA_BF16(c, a, b) \
    asm volatile("mma.sync.aligned.m16n8k16.row.col.f32.bf16.bf16.f32 " \
        "{%0,%1,%2,%3}, {%4,%5,%6,%7}, {%8,%9}, {%0,%1,%2,%3};" \
        : "+f"((c)[0]), "+f"((c)[1]), "+f"((c)[2]), "+f"((c)[3]) \
        : "r"((a)[0]), "r"((a)[1]), "r"((a)[2]), "r"((a)[3]), "r"((b)[0]), "r"((b)[1]))

// ---------------------------------------------------------------------------
__global__ void prep_pos_kernel(const float* __restrict__ qpos) {
    int i = blockIdx.x * blockDim.x + threadIdx.x;
    if (i >= ROWS) return;
    float x = qpos[i*3+0], y = qpos[i*3+1], z = qpos[i*3+2];
    float n = fmaf(z, z, fmaf(y, y, x * x));
    g_pos4[i] = make_float4(x, y, z, n);
}

__global__ void prep_A_kernel(const float* __restrict__ q) {
    int i = blockIdx.x * 256 + threadIdx.x;
    if (i >= ROWS * Cc / 4) return;
    float4 v = ((const float4*)q)[i];
    __nv_bfloat16 h0 = __float2bfloat16(v.x), h1 = __float2bfloat16(v.y);
    __nv_bfloat16 h2 = __float2bfloat16(v.z), h3 = __float2bfloat16(v.w);
    __nv_bfloat16 l0 = __float2bfloat16(v.x - __bfloat162float(h0));
    __nv_bfloat16 l1 = __float2bfloat16(v.y - __bfloat162float(h1));
    __nv_bfloat16 l2 = __float2bfloat16(v.z - __bfloat162float(h2));
    __nv_bfloat16 l3 = __float2bfloat16(v.w - __bfloat162float(h3));
    uint2 hh, ll;
    hh.x = ((uint32_t)__bfloat16_as_ushort(h1) << 16) | __bfloat16_as_ushort(h0);
    hh.y = ((uint32_t)__bfloat16_as_ushort(h3) << 16) | __bfloat16_as_ushort(h2);
    ll.x = ((uint32_t)__bfloat16_as_ushort(l1) << 16) | __bfloat16_as_ushort(l0);
    ll.y = ((uint32_t)__bfloat16_as_ushort(l3) << 16) | __bfloat16_as_ushort(l2);
    ((uint2*)g_Ah)[i] = hh;
    ((uint2*)g_Al)[i] = ll;
}

__global__ void prep_B_kernel(const float* __restrict__ W) {
    int i = blockIdx.x * 256 + threadIdx.x;
    if (i >= Ff * Cc) return;
    int n = i >> 8;
    int k = i & 255;
    float v;
    if (n < Cc) v = W[k * Cc + n];
    else        v = W[(Cc + k) * Cc + (n - Cc)] - W[k * Cc + (n - Cc)];
    __nv_bfloat16 h = __float2bfloat16(v);
    __nv_bfloat16 l = __float2bfloat16(v - __bfloat162float(h));
    g_Bh[i] = h;
    g_Bl[i] = l;
}

// ---------------------------------------------------------------------------
__global__ __launch_bounds__(512) void sort_kernel() {
    const int b   = blockIdx.x;
    const int tid = threadIdx.x;
    __shared__ unsigned sk[Nn];

    for (int i = tid; i < Nn; i += 512) {
        unsigned u = __float_as_uint(g_pos4[b*Nn + i].x);
        u = (u & 0x80000000u) ? ~u : (u | 0x80000000u);
        sk[i] = (u & 0xFFFFE000u) | (unsigned)i;
    }
    __syncthreads();

    for (int k = 2; k <= Nn; k <<= 1) {
        for (int j = k >> 1; j > 0; j >>= 1) {
            for (int t = tid; t < Nn/2; t += 512) {
                int i   = 2*t - (t & (j - 1));
                int ixj = i + j;
                unsigned a = sk[i], c = sk[ixj];
                bool asc = ((i & k) == 0);
                if ((a > c) == asc) { sk[i] = c; sk[ixj] = a; }
            }
            __syncthreads();
        }
    }

    for (int i = tid; i < Nn; i += 512) {
        int orig = (int)(sk[i] & 8191u);
        g_pos4s[b*Nn + i] = g_pos4[b*Nn + orig];
        g_sid  [b*Nn + i] = orig;
    }
}

// ---------------------------------------------------------------------------
// KNN v4 (round-13, unchanged): block-uniform exact tile pruning.
// ---------------------------------------------------------------------------
__global__ __launch_bounds__(256) void knn_kernel() {
    const int b    = blockIdx.y;
    const int tid  = threadIdx.x;
    const int w    = tid >> 5;
    const int lane = tid & 31;
    const int qb   = blockIdx.x * 32 + w * 4;

    const float4* __restrict__ pos = g_pos4s + b * Nn;
    const int*    __restrict__ sid = g_sid   + b * Nn;

    __shared__ float4         tile[1024];
    __shared__ float          ad[32][CAP];
    __shared__ unsigned short ai[32][CAP];
    __shared__ int            acnt[32];
    __shared__ float          wthrt[8];

    float qx[4], qy[4], qz[4], qn[4];
#pragma unroll
    for (int i = 0; i < 4; ++i) {
        float4 m = pos[qb + i];
        qx[i] = m.x; qy[i] = m.y; qz[i] = m.z; qn[i] = m.w;
    }

    const int ctile = blockIdx.x >> 5;

    if (tid < 32) acnt[tid] = 0;
    {
        const int t0 = ctile * 1024;
#pragma unroll
        for (int j = 0; j < 4; ++j)
            tile[tid + j * 256] = pos[t0 + tid + j * 256];
    }
    __syncthreads();

    float t1[4], t2[4];
#pragma unroll
    for (int i = 0; i < 4; ++i) { t1[i] = FLT_MAX; t2[i] = FLT_MAX; }

    for (int m = 0; m < 32; m += 4) {
        float4 c0 = tile[lane + (m + 0) * 32];
        float4 c1 = tile[lane + (m + 1) * 32];
        float4 c2 = tile[lane + (m + 2) * 32];
        float4 c3 = tile[lane + (m + 3) * 32];
#pragma unroll
        for (int i = 0; i < 4; ++i) {
            float d0 = fmaf(-2.0f, fmaf(qz[i], c0.z, fmaf(qy[i], c0.y, qx[i] * c0.x)), c0.w);
            float d1 = fmaf(-2.0f, fmaf(qz[i], c1.z, fmaf(qy[i], c1.y, qx[i] * c1.x)), c1.w);
            float d2 = fmaf(-2.0f, fmaf(qz[i], c2.z, fmaf(qy[i], c2.y, qx[i] * c2.x)), c2.w);
            float d3 = fmaf(-2.0f, fmaf(qz[i], c3.z, fmaf(qy[i], c3.y, qx[i] * c3.x)), c3.w);
            float mn01 = fminf(d0, d1), mx01 = fmaxf(d0, d1);
            float mn23 = fminf(d2, d3), mx23 = fmaxf(d2, d3);
            float s1 = fminf(mn01, mn23);
            float s2 = fminf(fmaxf(mn01, mn23), fminf(mx01, mx23));
            float nt1 = fminf(t1[i], s1);
            t2[i] = fminf(fmaxf(t1[i], s1), fminf(t2[i], s2));
            t1[i] = nt1;
        }
    }

    float thr[4];
#pragma unroll
    for (int i = 0; i < 4; ++i) {
        float a = t1[i], bb = t2[i];
        float m = FLT_MAX;
        for (int r = 0; r < 16; ++r) {
            float lo = fminf(a, bb);
            m = lo;
            m = fminf(m, __shfl_xor_sync(0xffffffffu, m, 1));
            m = fminf(m, __shfl_xor_sync(0xffffffffu, m, 2));
            m = fminf(m, __shfl_xor_sync(0xffffffffu, m, 4));
            m = fminf(m, __shfl_xor_sync(0xffffffffu, m, 8));
            m = fminf(m, __shfl_xor_sync(0xffffffffu, m, 16));
            unsigned msk = __ballot_sync(0xffffffffu, lo == m);
            int leader = __ffs(msk) - 1;
            if (lane == leader) {
                if (a <= bb) a = FLT_MAX; else bb = FLT_MAX;
            }
        }
        thr[i] = m;
    }

    {
        float wt = fmaxf(fmaxf(thr[0] + qn[0], thr[1] + qn[1]),
                         fmaxf(thr[2] + qn[2], thr[3] + qn[3]));
        if (lane == 0) wthrt[w] = wt;
    }
    __syncthreads();
    float maxthr_true = wthrt[0];
#pragma unroll
    for (int i = 1; i < 8; ++i) maxthr_true = fmaxf(maxthr_true, wthrt[i]);

    const float bqxlo = pos[blockIdx.x * 32].x;
    const float bqxhi = pos[blockIdx.x * 32 + 31].x;

    for (int ot = 0; ot < 8; ++ot) {
        const int tt = (ctile + ot) & 7;
        const int t0 = tt * 1024;
        if (ot > 0) {
            float gap = 0.0f;
            if (tt > ctile)      gap = pos[t0].x - bqxhi;
            else if (tt < ctile) gap = bqxlo - pos[t0 + 1023].x;
            if (gap > 0.0f && gap * gap > maxthr_true) continue;

            __syncthreads();
#pragma unroll
            for (int j = 0; j < 4; ++j)
                tile[tid + j * 256] = pos[t0 + tid + j * 256];
            __syncthreads();
        }
        for (int m = 0; m < 32; m += 4) {
            float4 c0 = tile[lane + (m + 0) * 32];
            float4 c1 = tile[lane + (m + 1) * 32];
            float4 c2 = tile[lane + (m + 2) * 32];
            float4 c3 = tile[lane + (m + 3) * 32];
#pragma unroll
            for (int i = 0; i < 4; ++i) {
                float d0 = fmaf(-2.0f, fmaf(qz[i], c0.z, fmaf(qy[i], c0.y, qx[i] * c0.x)), c0.w);
                float d1 = fmaf(-2.0f, fmaf(qz[i], c1.z, fmaf(qy[i], c1.y, qx[i] * c1.x)), c1.w);
                float d2 = fmaf(-2.0f, fmaf(qz[i], c2.z, fmaf(qy[i], c2.y, qx[i] * c2.x)), c2.w);
                float d3 = fmaf(-2.0f, fmaf(qz[i], c3.z, fmaf(qy[i], c3.y, qx[i] * c3.x)), c3.w);
                float mn = fminf(fminf(d0, d1), fminf(d2, d3));
                if (mn <= thr[i]) {
                    const int ql = w * 4 + i;
                    const int jb = t0 + lane + m * 32;
                    if (d0 <= thr[i]) {
                        int sl = atomicAdd(&acnt[ql], 1);
                        if (sl < CAP) { ad[ql][sl] = d0; ai[ql][sl] = (unsigned short)(jb); }
                    }
                    if (d1 <= thr[i]) {
                        int sl = atomicAdd(&acnt[ql], 1);
                        if (sl < CAP) { ad[ql][sl] = d1; ai[ql][sl] = (unsigned short)(jb + 32); }
                    }
                    if (d2 <= thr[i]) {
                        int sl = atomicAdd(&acnt[ql], 1);
                        if (sl < CAP) { ad[ql][sl] = d2; ai[ql][sl] = (unsigned short)(jb + 64); }
                    }
                    if (d3 <= thr[i]) {
                        int sl = atomicAdd(&acnt[ql], 1);
                        if (sl < CAP) { ad[ql][sl] = d3; ai[ql][sl] = (unsigned short)(jb + 96); }
                    }
                }
            }
        }
    }
    __syncthreads();

    if (tid < 32) {
        const int cntRaw = acnt[tid];
        const int cnt    = cntRaw < CAP ? cntRaw : CAP;
        float md[Kk]; int mi[Kk];
#pragma unroll
        for (int i = 0; i < Kk; ++i) { md[i] = FLT_MAX; mi[i] = 0; }
        float mthr = FLT_MAX;
        for (int t = 0; t < cnt; ++t) {
            float cd = ad[tid][t];
            if (cd < mthr) {
                int ci = ai[tid][t];
#pragma unroll
                for (int u = 0; u < Kk; ++u) {
                    bool  sw = cd < md[u];
                    float od = md[u]; int oi = mi[u];
                    md[u] = sw ? cd : od;  mi[u] = sw ? ci : oi;
                    cd    = sw ? od : cd;  ci    = sw ? oi : ci;
                }
                mthr = md[Kk - 1];
            }
        }
        const int orig = sid[blockIdx.x * 32 + tid];
        const int gq   = b * Nn + orig;
        g_ovf[gq] = (cntRaw > CAP) ? 1 : 0;
#pragma unroll
        for (int i = 0; i < Kk; ++i) g_idx[gq * Kk + i] = sid[mi[i]];
    }
}

// ---------------------------------------------------------------------------
__global__ __launch_bounds__(256) void knn_fix_kernel() {
    const int i = blockIdx.x * 256 + threadIdx.x;
    if (i >= ROWS) return;
    if (!g_ovf[i]) return;
    const int b = i >> 13;
    const float4* __restrict__ pos = g_pos4 + b * Nn;
    float4 me = pos[i & 8191];
    const float qx = me.x, qy = me.y, qz = me.z;
    float dist[Kk]; int nid[Kk];
#pragma unroll
    for (int t = 0; t < Kk; ++t) { dist[t] = FLT_MAX; nid[t] = 0; }
    float thr = FLT_MAX;
    for (int j = 0; j < Nn; ++j) {
        float4 cp = pos[j];
        float d2 = fmaf(-2.0f, fmaf(qz, cp.z, fmaf(qy, cp.y, qx * cp.x)), cp.w);
        if (d2 < thr) {
            float cd = d2; int ci = j;
#pragma unroll
            for (int t = 0; t < Kk; ++t) {
                bool  sw = cd < dist[t];
                float od = dist[t]; int oi = nid[t];
                dist[t] = sw ? cd : od;  nid[t] = sw ? ci : oi;
                cd      = sw ? od : cd;  ci     = sw ? oi : ci;
            }
            thr = dist[Kk - 1];
        }
    }
#pragma unroll
    for (int t = 0; t < Kk; ++t) g_idx[i * Kk + t] = nid[t];
}

// ---------------------------------------------------------------------------
// bf16-split GEMM via warp-level mma.sync (HMMA).
// Epilogue: P columns (bn0 < 256) -> g_Ph as fp16; U columns -> g_U as fp32.
// ---------------------------------------------------------------------------
__global__ __launch_bounds__(256) void gemm_mma_kernel() {
    __shared__ __nv_bfloat16 sAh[128][40];
    __shared__ __nv_bfloat16 sAl[128][40];
    __shared__ __nv_bfloat16 sBh[128][40];
    __shared__ __nv_bfloat16 sBl[128][40];

    const int tid  = threadIdx.x;
    const int wid  = tid >> 5;
    const int lane = tid & 31;
    const int wm   = wid >> 2;
    const int wn   = wid & 3;
    const int bm0  = blockIdx.x * 128;
    const int bn0  = blockIdx.y * 128;

    float acc[4][4][4];
#pragma unroll
    for (int mt = 0; mt < 4; ++mt)
#pragma unroll
        for (int nt = 0; nt < 4; ++nt)
#pragma unroll
            for (int i = 0; i < 4; ++i) acc[mt][nt][i] = 0.0f;

    const int a_sub = lane >> 3, a_r = lane & 7;
    const int a_row_off = (a_sub & 1) * 8 + a_r;
    const int a_col_off = (a_sub >> 1) * 8;
    const int b_sub = (lane >> 3) & 1, b_r = lane & 7;

    for (int kt = 0; kt < 8; ++kt) {
        const int k0 = kt * 32;
#pragma unroll
        for (int half = 0; half < 2; ++half) {
            const int gi  = tid + half * 256;
            const int row = gi >> 2;
            const int g   = gi & 3;
            const size_t aoff = (size_t)(bm0 + row) * Cc + k0 + g * 8;
            const size_t boff = (size_t)(bn0 + row) * Cc + k0 + g * 8;
            *(uint4*)&sAh[row][g * 8] = *(const uint4*)(g_Ah + aoff);
            *(uint4*)&sAl[row][g * 8] = *(const uint4*)(g_Al + aoff);
            *(uint4*)&sBh[row][g * 8] = *(const uint4*)(g_Bh + boff);
            *(uint4*)&sBl[row][g * 8] = *(const uint4*)(g_Bl + boff);
        }
        __syncthreads();

#pragma unroll
        for (int kh = 0; kh < 32; kh += 16) {
            uint32_t ah[4][4], al[4][4], bh[4][2], bl[4][2];
#pragma unroll
            for (int mt = 0; mt < 4; ++mt) {
                const int arow = wm * 64 + mt * 16 + a_row_off;
                const int acol = kh + a_col_off;
                LDSM_X4(ah[mt], smem_u32(&sAh[arow][acol]));
                LDSM_X4(al[mt], smem_u32(&sAl[arow][acol]));
            }
#pragma unroll
            for (int nt = 0; nt < 4; ++nt) {
                const int brow = wn * 32 + nt * 8 + b_r;
                const int bcol = kh + b_sub * 8;
                LDSM_X2(bh[nt], smem_u32(&sBh[brow][bcol]));
                LDSM_X2(bl[nt], smem_u32(&sBl[brow][bcol]));
            }
#pragma unroll
            for (int mt = 0; mt < 4; ++mt)
#pragma unroll
                for (int nt = 0; nt < 4; ++nt) {
                    MMA_BF16(acc[mt][nt], ah[mt], bh[nt]);
                    MMA_BF16(acc[mt][nt], ah[mt], bl[nt]);
                    MMA_BF16(acc[mt][nt], al[mt], bh[nt]);
                }
        }
        __syncthreads();
    }

    const int g   = lane >> 2;
    const int tig = lane & 3;
    if (bn0 < Cc) {
        // P tile -> fp16
#pragma unroll
        for (int mt = 0; mt < 4; ++mt)
#pragma unroll
            for (int nt = 0; nt < 4; ++nt) {
                const int row = bm0 + wm * 64 + mt * 16 + g;
                const int col = bn0 + wn * 32 + nt * 8 + tig * 2;
                __half2 h0 = __floats2half2_rn(acc[mt][nt][0], acc[mt][nt][1]);
                __half2 h1 = __floats2half2_rn(acc[mt][nt][2], acc[mt][nt][3]);
                *(__half2*)(g_Ph + (size_t)row * Cc + col)       = h0;
                *(__half2*)(g_Ph + (size_t)(row + 8) * Cc + col) = h1;
            }
    } else {
        // U tile -> fp32
#pragma unroll
        for (int mt = 0; mt < 4; ++mt)
#pragma unroll
            for (int nt = 0; nt < 4; ++nt) {
                const int row = bm0 + wm * 64 + mt * 16 + g;
                const int col = (bn0 - Cc) + wn * 32 + nt * 8 + tig * 2;
                float2 v0 = make_float2(acc[mt][nt][0], acc[mt][nt][1]);
                float2 v1 = make_float2(acc[mt][nt][2], acc[mt][nt][3]);
                *(float2*)(g_U + (size_t)row * Cc + col)       = v0;
                *(float2*)(g_U + (size_t)(row + 8) * Cc + col) = v1;
            }
    }
}

// ---------------------------------------------------------------------------
// gather+max over fp16 P rows (512B per neighbor row; 1 LDG.128 per lane).
// ---------------------------------------------------------------------------
__global__ __launch_bounds__(256) void gather_max_kernel(const float* __restrict__ bias,
                                                         float* __restrict__ out) {
    const int row  = blockIdx.x * 8 + (threadIdx.x >> 5);
    const int lane = threadIdx.x & 31;
    const int b    = row >> 13;

    const int* ir = g_idx + row * Kk;
    int myn = ir[lane & (Kk - 1)];

    const __half* Pbase = g_Ph + (size_t)(b << 13) * Cc;

    __half2 m0 = __floats2half2_rn(-65504.f, -65504.f);
    __half2 m1 = m0, m2 = m0, m3 = m0;

#pragma unroll
    for (int j = 0; j < Kk; ++j) {
        int nb = __shfl_sync(0xffffffffu, myn, j);
        uint4 v = ((const uint4*)(Pbase + (size_t)nb * Cc))[lane];
        m0 = __hmax2(m0, *reinterpret_cast<__half2*>(&v.x));
        m1 = __hmax2(m1, *reinterpret_cast<__half2*>(&v.y));
        m2 = __hmax2(m2, *reinterpret_cast<__half2*>(&v.z));
        m3 = __hmax2(m3, *reinterpret_cast<__half2*>(&v.w));
    }

    float2 f0 = __half22float2(m0), f1 = __half22float2(m1);
    float2 f2 = __half22float2(m2), f3 = __half22float2(m3);

    const float4* Ur = (const float4*)(g_U + (size_t)row * Cc);
    float4 u0 = Ur[lane * 2], u1 = Ur[lane * 2 + 1];
    const float4* Br = (const float4*)bias;
    float4 bb0 = Br[lane * 2], bb1 = Br[lane * 2 + 1];

    float4 v0, v1;
    v0.x = f0.x + u0.x + bb0.x; v0.y = f0.y + u0.y + bb0.y;
    v0.z = f1.x + u0.z + bb0.z; v0.w = f1.y + u0.w + bb0.w;
    v1.x = f2.x + u1.x + bb1.x; v1.y = f2.y + u1.y + bb1.y;
    v1.z = f3.x + u1.z + bb1.z; v1.w = f3.y + u1.w + bb1.w;

    v0.x = fmaxf(v0.x, 0.2f * v0.x); v0.y = fmaxf(v0.y, 0.2f * v0.y);
    v0.z = fmaxf(v0.z, 0.2f * v0.z); v0.w = fmaxf(v0.w, 0.2f * v0.w);
    v1.x = fmaxf(v1.x, 0.2f * v1.x); v1.y = fmaxf(v1.y, 0.2f * v1.y);
    v1.z = fmaxf(v1.z, 0.2f * v1.z); v1.w = fmaxf(v1.w, 0.2f * v1.w);

    float4* Or = (float4*)(out + (size_t)row * Cc);
    Or[lane * 2]     = v0;
    Or[lane * 2 + 1] = v1;
}

// ---------------------------------------------------------------------------
extern "C" void kernel_launch(void* const* d_in, const int* in_sizes, int n_in,
                              void* d_out, int out_size) {
    const float* q    = (const float*)d_in[0];   // [4,8192,256]
    const float* qpos = (const float*)d_in[1];   // [4,8192,3]
    const float* W    = (const float*)d_in[2];   // [512,256]
    const float* bias = (const float*)d_in[3];   // [256]
    float* out = (float*)d_out;
    (void)in_sizes; (void)n_in; (void)out_size;

    cudaStream_t s2;
    cudaEvent_t eFork, eJoin;
    cudaStreamCreateWithFlags(&s2, cudaStreamNonBlocking);
    cudaEventCreateWithFlags(&eFork, cudaEventDisableTiming);
    cudaEventCreateWithFlags(&eJoin, cudaEventDisableTiming);

    cudaEventRecord(eFork, 0);
    cudaStreamWaitEvent(s2, eFork, 0);

    // --- side branch: GEMM chain ---
    prep_A_kernel<<<(ROWS * Cc / 4 + 255) / 256, 256, 0, s2>>>(q);
    prep_B_kernel<<<(Ff * Cc + 255) / 256, 256, 0, s2>>>(W);
    gemm_mma_kernel<<<dim3(ROWS / 128, Ff / 128), 256, 0, s2>>>();
    cudaEventRecord(eJoin, s2);

    // --- main branch: KNN chain ---
    prep_pos_kernel<<<(ROWS + 255) / 256, 256>>>(qpos);
    sort_kernel<<<Bn, 512>>>();
    knn_kernel<<<dim3(Nn / 32, Bn), 256>>>();
    knn_fix_kernel<<<ROWS / 256, 256>>>();

    // --- join, then epilogue ---
    cudaStreamWaitEvent(0, eJoin, 0);
    gather_max_kernel<<<ROWS / 8, 256>>>(bias, out);
}

// round 16
// speedup vs baseline: 2.3076x; 1.0591x over previous
#include <cuda_runtime.h>
#include <cuda_bf16.h>
#include <cuda_fp16.h>
#include <float.h>
#include <stdint.h>

#define Bn   4
#define Nn   8192
#define Cc   256
#define Kk   16
#define Ff   512
#define ROWS (Bn*Nn)
#define CAP  128

__device__ float4 g_pos4 [ROWS];
__device__ float4 g_pos4s[ROWS];
__device__ int    g_sid  [ROWS];
__device__ int    g_ovf  [ROWS];
__device__ __half g_Ph[(size_t)ROWS * Cc];   // P = q@Wa   (fp16, gather-only)
__device__ float  g_U [(size_t)ROWS * Cc];   // U = q@(Wb-Wa)  (fp32)
__device__ int    g_idx[ROWS * Kk];
__device__ __nv_bfloat16 g_Ah[(size_t)ROWS * Cc];
__device__ __nv_bfloat16 g_Al[(size_t)ROWS * Cc];
__device__ __nv_bfloat16 g_Bh[Ff * Cc];   // B^T: [n][k]
__device__ __nv_bfloat16 g_Bl[Ff * Cc];

__device__ __forceinline__ uint32_t smem_u32(const void* p) {
    uint32_t a;
    asm("{ .reg .u64 t; cvta.to.shared.u64 t, %1; cvt.u32.u64 %0, t; }" : "=r"(a) : "l"(p));
    return a;
}
#define LDSM_X4(r, addr) \
    asm volatile("ldmatrix.sync.aligned.m8n8.x4.shared.b16 {%0,%1,%2,%3}, [%4];" \
        : "=r"((r)[0]), "=r"((r)[1]), "=r"((r)[2]), "=r"((r)[3]) : "r"(addr))
#define LDSM_X2(r, addr) \
    asm volatile("ldmatrix.sync.aligned.m8n8.x2.shared.b16 {%0,%1}, [%2];" \
        : "=r"((r)[0]), "=r"((r)[1]) : "r"(addr))
#define MMA_BF16(c, a, b) \
    asm volatile("mma.sync.aligned.m16n8k16.row.col.f32.bf16.bf16.f32 " \
        "{%0,%1,%2,%3}, {%4,%5,%6,%7}, {%8,%9}, {%0,%1,%2,%3};" \
        : "+f"((c)[0]), "+f"((c)[1]), "+f"((c)[2]), "+f"((c)[3]) \
        : "r"((a)[0]), "r"((a)[1]), "r"((a)[2]), "r"((a)[3]), "r"((b)[0]), "r"((b)[1]))

// ---------------------------------------------------------------------------
__global__ void prep_pos_kernel(const float* __restrict__ qpos) {
    int i = blockIdx.x * blockDim.x + threadIdx.x;
    if (i >= ROWS) return;
    float x = qpos[i*3+0], y = qpos[i*3+1], z = qpos[i*3+2];
    float n = fmaf(z, z, fmaf(y, y, x * x));
    g_pos4[i] = make_float4(x, y, z, n);
}

__global__ void prep_A_kernel(const float* __restrict__ q) {
    int i = blockIdx.x * 256 + threadIdx.x;
    if (i >= ROWS * Cc / 4) return;
    float4 v = ((const float4*)q)[i];
    __nv_bfloat16 h0 = __float2bfloat16(v.x), h1 = __float2bfloat16(v.y);
    __nv_bfloat16 h2 = __float2bfloat16(v.z), h3 = __float2bfloat16(v.w);
    __nv_bfloat16 l0 = __float2bfloat16(v.x - __bfloat162float(h0));
    __nv_bfloat16 l1 = __float2bfloat16(v.y - __bfloat162float(h1));
    __nv_bfloat16 l2 = __float2bfloat16(v.z - __bfloat162float(h2));
    __nv_bfloat16 l3 = __float2bfloat16(v.w - __bfloat162float(h3));
    uint2 hh, ll;
    hh.x = ((uint32_t)__bfloat16_as_ushort(h1) << 16) | __bfloat16_as_ushort(h0);
    hh.y = ((uint32_t)__bfloat16_as_ushort(h3) << 16) | __bfloat16_as_ushort(h2);
    ll.x = ((uint32_t)__bfloat16_as_ushort(l1) << 16) | __bfloat16_as_ushort(l0);
    ll.y = ((uint32_t)__bfloat16_as_ushort(l3) << 16) | __bfloat16_as_ushort(l2);
    ((uint2*)g_Ah)[i] = hh;
    ((uint2*)g_Al)[i] = ll;
}

__global__ void prep_B_kernel(const float* __restrict__ W) {
    int i = blockIdx.x * 256 + threadIdx.x;
    if (i >= Ff * Cc) return;
    int n = i >> 8;
    int k = i & 255;
    float v;
    if (n < Cc) v = W[k * Cc + n];
    else        v = W[(Cc + k) * Cc + (n - Cc)] - W[k * Cc + (n - Cc)];
    __nv_bfloat16 h = __float2bfloat16(v);
    __nv_bfloat16 l = __float2bfloat16(v - __bfloat162float(h));
    g_Bh[i] = h;
    g_Bl[i] = l;
}

// ---------------------------------------------------------------------------
__global__ __launch_bounds__(1024) void sort_kernel() {
    const int b   = blockIdx.x;
    const int tid = threadIdx.x;
    __shared__ unsigned sk[Nn];

    for (int i = tid; i < Nn; i += 1024) {
        unsigned u = __float_as_uint(g_pos4[b*Nn + i].x);
        u = (u & 0x80000000u) ? ~u : (u | 0x80000000u);
        sk[i] = (u & 0xFFFFE000u) | (unsigned)i;
    }
    __syncthreads();

    for (int k = 2; k <= Nn; k <<= 1) {
        for (int j = k >> 1; j > 0; j >>= 1) {
            for (int t = tid; t < Nn/2; t += 1024) {
                int i   = 2*t - (t & (j - 1));
                int ixj = i + j;
                unsigned a = sk[i], c = sk[ixj];
                bool asc = ((i & k) == 0);
                if ((a > c) == asc) { sk[i] = c; sk[ixj] = a; }
            }
            __syncthreads();
        }
    }

    for (int i = tid; i < Nn; i += 1024) {
        int orig = (int)(sk[i] & 8191u);
        g_pos4s[b*Nn + i] = g_pos4[b*Nn + orig];
        g_sid  [b*Nn + i] = orig;
    }
}

// ---------------------------------------------------------------------------
// KNN v5: v4 + per-warp scan skip. Block-level skip (load) uses block max
// threshold; each warp additionally skips the scan of a loaded tile when its
// own 4-query bound excludes it. Both bounds are exact.
// ---------------------------------------------------------------------------
__global__ __launch_bounds__(256) void knn_kernel() {
    const int b    = blockIdx.y;
    const int tid  = threadIdx.x;
    const int w    = tid >> 5;
    const int lane = tid & 31;
    const int qb   = blockIdx.x * 32 + w * 4;

    const float4* __restrict__ pos = g_pos4s + b * Nn;
    const int*    __restrict__ sid = g_sid   + b * Nn;

    __shared__ float4         tile[1024];
    __shared__ float          ad[32][CAP];
    __shared__ unsigned short ai[32][CAP];
    __shared__ int            acnt[32];
    __shared__ float          wthrt[8];

    float qx[4], qy[4], qz[4], qn[4];
#pragma unroll
    for (int i = 0; i < 4; ++i) {
        float4 m = pos[qb + i];
        qx[i] = m.x; qy[i] = m.y; qz[i] = m.z; qn[i] = m.w;
    }
    const float wqxlo = qx[0];           // warp's queries are x-sorted
    const float wqxhi = qx[3];

    const int ctile = blockIdx.x >> 5;

    if (tid < 32) acnt[tid] = 0;
    {
        const int t0 = ctile * 1024;
#pragma unroll
        for (int j = 0; j < 4; ++j)
            tile[tid + j * 256] = pos[t0 + tid + j * 256];
    }
    __syncthreads();

    float t1[4], t2[4];
#pragma unroll
    for (int i = 0; i < 4; ++i) { t1[i] = FLT_MAX; t2[i] = FLT_MAX; }

    for (int m = 0; m < 32; m += 4) {
        float4 c0 = tile[lane + (m + 0) * 32];
        float4 c1 = tile[lane + (m + 1) * 32];
        float4 c2 = tile[lane + (m + 2) * 32];
        float4 c3 = tile[lane + (m + 3) * 32];
#pragma unroll
        for (int i = 0; i < 4; ++i) {
            float d0 = fmaf(-2.0f, fmaf(qz[i], c0.z, fmaf(qy[i], c0.y, qx[i] * c0.x)), c0.w);
            float d1 = fmaf(-2.0f, fmaf(qz[i], c1.z, fmaf(qy[i], c1.y, qx[i] * c1.x)), c1.w);
            float d2 = fmaf(-2.0f, fmaf(qz[i], c2.z, fmaf(qy[i], c2.y, qx[i] * c2.x)), c2.w);
            float d3 = fmaf(-2.0f, fmaf(qz[i], c3.z, fmaf(qy[i], c3.y, qx[i] * c3.x)), c3.w);
            float mn01 = fminf(d0, d1), mx01 = fmaxf(d0, d1);
            float mn23 = fminf(d2, d3), mx23 = fmaxf(d2, d3);
            float s1 = fminf(mn01, mn23);
            float s2 = fminf(fmaxf(mn01, mn23), fminf(mx01, mx23));
            float nt1 = fminf(t1[i], s1);
            t2[i] = fminf(fmaxf(t1[i], s1), fminf(t2[i], s2));
            t1[i] = nt1;
        }
    }

    float thr[4];
#pragma unroll
    for (int i = 0; i < 4; ++i) {
        float a = t1[i], bb = t2[i];
        float m = FLT_MAX;
        for (int r = 0; r < 16; ++r) {
            float lo = fminf(a, bb);
            m = lo;
            m = fminf(m, __shfl_xor_sync(0xffffffffu, m, 1));
            m = fminf(m, __shfl_xor_sync(0xffffffffu, m, 2));
            m = fminf(m, __shfl_xor_sync(0xffffffffu, m, 4));
            m = fminf(m, __shfl_xor_sync(0xffffffffu, m, 8));
            m = fminf(m, __shfl_xor_sync(0xffffffffu, m, 16));
            unsigned msk = __ballot_sync(0xffffffffu, lo == m);
            int leader = __ffs(msk) - 1;
            if (lane == leader) {
                if (a <= bb) a = FLT_MAX; else bb = FLT_MAX;
            }
        }
        thr[i] = m;
    }

    // per-warp max true-space threshold (kept in register) + block max
    float mywt = fmaxf(fmaxf(thr[0] + qn[0], thr[1] + qn[1]),
                       fmaxf(thr[2] + qn[2], thr[3] + qn[3]));
    if (lane == 0) wthrt[w] = mywt;
    __syncthreads();
    float maxthr_true = wthrt[0];
#pragma unroll
    for (int i = 1; i < 8; ++i) maxthr_true = fmaxf(maxthr_true, wthrt[i]);

    const float bqxlo = pos[blockIdx.x * 32].x;
    const float bqxhi = pos[blockIdx.x * 32 + 31].x;

    for (int ot = 0; ot < 8; ++ot) {
        const int tt = (ctile + ot) & 7;
        const int t0 = tt * 1024;
        if (ot > 0) {
            // block-uniform load skip
            float gap = 0.0f;
            if (tt > ctile)      gap = pos[t0].x - bqxhi;
            else if (tt < ctile) gap = bqxlo - pos[t0 + 1023].x;
            if (gap > 0.0f && gap * gap > maxthr_true) continue;

            __syncthreads();
#pragma unroll
            for (int j = 0; j < 4; ++j)
                tile[tid + j * 256] = pos[t0 + tid + j * 256];
            __syncthreads();

            // per-warp scan skip (tighter bound; no barriers in scan body)
            float wgap = 0.0f;
            if (tt > ctile)      wgap = pos[t0].x - wqxhi;
            else if (tt < ctile) wgap = wqxlo - pos[t0 + 1023].x;
            if (wgap > 0.0f && wgap * wgap > mywt) continue;
        }
        for (int m = 0; m < 32; m += 4) {
            float4 c0 = tile[lane + (m + 0) * 32];
            float4 c1 = tile[lane + (m + 1) * 32];
            float4 c2 = tile[lane + (m + 2) * 32];
            float4 c3 = tile[lane + (m + 3) * 32];
#pragma unroll
            for (int i = 0; i < 4; ++i) {
                float d0 = fmaf(-2.0f, fmaf(qz[i], c0.z, fmaf(qy[i], c0.y, qx[i] * c0.x)), c0.w);
                float d1 = fmaf(-2.0f, fmaf(qz[i], c1.z, fmaf(qy[i], c1.y, qx[i] * c1.x)), c1.w);
                float d2 = fmaf(-2.0f, fmaf(qz[i], c2.z, fmaf(qy[i], c2.y, qx[i] * c2.x)), c2.w);
                float d3 = fmaf(-2.0f, fmaf(qz[i], c3.z, fmaf(qy[i], c3.y, qx[i] * c3.x)), c3.w);
                float mn = fminf(fminf(d0, d1), fminf(d2, d3));
                if (mn <= thr[i]) {
                    const int ql = w * 4 + i;
                    const int jb = t0 + lane + m * 32;
                    if (d0 <= thr[i]) {
                        int sl = atomicAdd(&acnt[ql], 1);
                        if (sl < CAP) { ad[ql][sl] = d0; ai[ql][sl] = (unsigned short)(jb); }
                    }
                    if (d1 <= thr[i]) {
                        int sl = atomicAdd(&acnt[ql], 1);
                        if (sl < CAP) { ad[ql][sl] = d1; ai[ql][sl] = (unsigned short)(jb + 32); }
                    }
                    if (d2 <= thr[i]) {
                        int sl = atomicAdd(&acnt[ql], 1);
                        if (sl < CAP) { ad[ql][sl] = d2; ai[ql][sl] = (unsigned short)(jb + 64); }
                    }
                    if (d3 <= thr[i]) {
                        int sl = atomicAdd(&acnt[ql], 1);
                        if (sl < CAP) { ad[ql][sl] = d3; ai[ql][sl] = (unsigned short)(jb + 96); }
                    }
                }
            }
        }
    }
    __syncthreads();

    if (tid < 32) {
        const int cntRaw = acnt[tid];
        const int cnt    = cntRaw < CAP ? cntRaw : CAP;
        float md[Kk]; int mi[Kk];
#pragma unroll
        for (int i = 0; i < Kk; ++i) { md[i] = FLT_MAX; mi[i] = 0; }
        float mthr = FLT_MAX;
        for (int t = 0; t < cnt; ++t) {
            float cd = ad[tid][t];
            if (cd < mthr) {
                int ci = ai[tid][t];
#pragma unroll
                for (int u = 0; u < Kk; ++u) {
                    bool  sw = cd < md[u];
                    float od = md[u]; int oi = mi[u];
                    md[u] = sw ? cd : od;  mi[u] = sw ? ci : oi;
                    cd    = sw ? od : cd;  ci    = sw ? oi : ci;
                }
                mthr = md[Kk - 1];
            }
        }
        const int orig = sid[blockIdx.x * 32 + tid];
        const int gq   = b * Nn + orig;
        g_ovf[gq] = (cntRaw > CAP) ? 1 : 0;
#pragma unroll
        for (int i = 0; i < Kk; ++i) g_idx[gq * Kk + i] = sid[mi[i]];
    }
}

// ---------------------------------------------------------------------------
__global__ __launch_bounds__(256) void knn_fix_kernel() {
    const int i = blockIdx.x * 256 + threadIdx.x;
    if (i >= ROWS) return;
    if (!g_ovf[i]) return;
    const int b = i >> 13;
    const float4* __restrict__ pos = g_pos4 + b * Nn;
    float4 me = pos[i & 8191];
    const float qx = me.x, qy = me.y, qz = me.z;
    float dist[Kk]; int nid[Kk];
#pragma unroll
    for (int t = 0; t < Kk; ++t) { dist[t] = FLT_MAX; nid[t] = 0; }
    float thr = FLT_MAX;
    for (int j = 0; j < Nn; ++j) {
        float4 cp = pos[j];
        float d2 = fmaf(-2.0f, fmaf(qz, cp.z, fmaf(qy, cp.y, qx * cp.x)), cp.w);
        if (d2 < thr) {
            float cd = d2; int ci = j;
#pragma unroll
            for (int t = 0; t < Kk; ++t) {
                bool  sw = cd < dist[t];
                float od = dist[t]; int oi = nid[t];
                dist[t] = sw ? cd : od;  nid[t] = sw ? ci : oi;
                cd      = sw ? od : cd;  ci     = sw ? oi : ci;
            }
            thr = dist[Kk - 1];
        }
    }
#pragma unroll
    for (int t = 0; t < Kk; ++t) g_idx[i * Kk + t] = nid[t];
}

// ---------------------------------------------------------------------------
// bf16-split GEMM via warp-level mma.sync (HMMA).
// Epilogue: P columns (bn0 < 256) -> g_Ph as fp16; U columns -> g_U as fp32.
// ---------------------------------------------------------------------------
__global__ __launch_bounds__(256) void gemm_mma_kernel() {
    __shared__ __nv_bfloat16 sAh[128][40];
    __shared__ __nv_bfloat16 sAl[128][40];
    __shared__ __nv_bfloat16 sBh[128][40];
    __shared__ __nv_bfloat16 sBl[128][40];

    const int tid  = threadIdx.x;
    const int wid  = tid >> 5;
    const int lane = tid & 31;
    const int wm   = wid >> 2;
    const int wn   = wid & 3;
    const int bm0  = blockIdx.x * 128;
    const int bn0  = blockIdx.y * 128;

    float acc[4][4][4];
#pragma unroll
    for (int mt = 0; mt < 4; ++mt)
#pragma unroll
        for (int nt = 0; nt < 4; ++nt)
#pragma unroll
            for (int i = 0; i < 4; ++i) acc[mt][nt][i] = 0.0f;

    const int a_sub = lane >> 3, a_r = lane & 7;
    const int a_row_off = (a_sub & 1) * 8 + a_r;
    const int a_col_off = (a_sub >> 1) * 8;
    const int b_sub = (lane >> 3) & 1, b_r = lane & 7;

    for (int kt = 0; kt < 8; ++kt) {
        const int k0 = kt * 32;
#pragma unroll
        for (int half = 0; half < 2; ++half) {
            const int gi  = tid + half * 256;
            const int row = gi >> 2;
            const int g   = gi & 3;
            const size_t aoff = (size_t)(bm0 + row) * Cc + k0 + g * 8;
            const size_t boff = (size_t)(bn0 + row) * Cc + k0 + g * 8;
            *(uint4*)&sAh[row][g * 8] = *(const uint4*)(g_Ah + aoff);
            *(uint4*)&sAl[row][g * 8] = *(const uint4*)(g_Al + aoff);
            *(uint4*)&sBh[row][g * 8] = *(const uint4*)(g_Bh + boff);
            *(uint4*)&sBl[row][g * 8] = *(const uint4*)(g_Bl + boff);
        }
        __syncthreads();

#pragma unroll
        for (int kh = 0; kh < 32; kh += 16) {
            uint32_t ah[4][4], al[4][4], bh[4][2], bl[4][2];
#pragma unroll
            for (int mt = 0; mt < 4; ++mt) {
                const int arow = wm * 64 + mt * 16 + a_row_off;
                const int acol = kh + a_col_off;
                LDSM_X4(ah[mt], smem_u32(&sAh[arow][acol]));
                LDSM_X4(al[mt], smem_u32(&sAl[arow][acol]));
            }
#pragma unroll
            for (int nt = 0; nt < 4; ++nt) {
                const int brow = wn * 32 + nt * 8 + b_r;
                const int bcol = kh + b_sub * 8;
                LDSM_X2(bh[nt], smem_u32(&sBh[brow][bcol]));
                LDSM_X2(bl[nt], smem_u32(&sBl[brow][bcol]));
            }
#pragma unroll
            for (int mt = 0; mt < 4; ++mt)
#pragma unroll
                for (int nt = 0; nt < 4; ++nt) {
                    MMA_BF16(acc[mt][nt], ah[mt], bh[nt]);
                    MMA_BF16(acc[mt][nt], ah[mt], bl[nt]);
                    MMA_BF16(acc[mt][nt], al[mt], bh[nt]);
                }
        }
        __syncthreads();
    }

    const int g   = lane >> 2;
    const int tig = lane & 3;
    if (bn0 < Cc) {
#pragma unroll
        for (int mt = 0; mt < 4; ++mt)
#pragma unroll
            for (int nt = 0; nt < 4; ++nt) {
                const int row = bm0 + wm * 64 + mt * 16 + g;
                const int col = bn0 + wn * 32 + nt * 8 + tig * 2;
                __half2 h0 = __floats2half2_rn(acc[mt][nt][0], acc[mt][nt][1]);
                __half2 h1 = __floats2half2_rn(acc[mt][nt][2], acc[mt][nt][3]);
                *(__half2*)(g_Ph + (size_t)row * Cc + col)       = h0;
                *(__half2*)(g_Ph + (size_t)(row + 8) * Cc + col) = h1;
            }
    } else {
#pragma unroll
        for (int mt = 0; mt < 4; ++mt)
#pragma unroll
            for (int nt = 0; nt < 4; ++nt) {
                const int row = bm0 + wm * 64 + mt * 16 + g;
                const int col = (bn0 - Cc) + wn * 32 + nt * 8 + tig * 2;
                float2 v0 = make_float2(acc[mt][nt][0], acc[mt][nt][1]);
                float2 v1 = make_float2(acc[mt][nt][2], acc[mt][nt][3]);
                *(float2*)(g_U + (size_t)row * Cc + col)       = v0;
                *(float2*)(g_U + (size_t)(row + 8) * Cc + col) = v1;
            }
    }
}

// ---------------------------------------------------------------------------
__global__ __launch_bounds__(256) void gather_max_kernel(const float* __restrict__ bias,
                                                         float* __restrict__ out) {
    const int row  = blockIdx.x * 8 + (threadIdx.x >> 5);
    const int lane = threadIdx.x & 31;
    const int b    = row >> 13;

    const int* ir = g_idx + row * Kk;
    int myn = ir[lane & (Kk - 1)];

    const __half* Pbase = g_Ph + (size_t)(b << 13) * Cc;

    __half2 m0 = __floats2half2_rn(-65504.f, -65504.f);
    __half2 m1 = m0, m2 = m0, m3 = m0;

#pragma unroll
    for (int j = 0; j < Kk; ++j) {
        int nb = __shfl_sync(0xffffffffu, myn, j);
        uint4 v = ((const uint4*)(Pbase + (size_t)nb * Cc))[lane];
        m0 = __hmax2(m0, *reinterpret_cast<__half2*>(&v.x));
        m1 = __hmax2(m1, *reinterpret_cast<__half2*>(&v.y));
        m2 = __hmax2(m2, *reinterpret_cast<__half2*>(&v.z));
        m3 = __hmax2(m3, *reinterpret_cast<__half2*>(&v.w));
    }

    float2 f0 = __half22float2(m0), f1 = __half22float2(m1);
    float2 f2 = __half22float2(m2), f3 = __half22float2(m3);

    const float4* Ur = (const float4*)(g_U + (size_t)row * Cc);
    float4 u0 = Ur[lane * 2], u1 = Ur[lane * 2 + 1];
    const float4* Br = (const float4*)bias;
    float4 bb0 = Br[lane * 2], bb1 = Br[lane * 2 + 1];

    float4 v0, v1;
    v0.x = f0.x + u0.x + bb0.x; v0.y = f0.y + u0.y + bb0.y;
    v0.z = f1.x + u0.z + bb0.z; v0.w = f1.y + u0.w + bb0.w;
    v1.x = f2.x + u1.x + bb1.x; v1.y = f2.y + u1.y + bb1.y;
    v1.z = f3.x + u1.z + bb1.z; v1.w = f3.y + u1.w + bb1.w;

    v0.x = fmaxf(v0.x, 0.2f * v0.x); v0.y = fmaxf(v0.y, 0.2f * v0.y);
    v0.z = fmaxf(v0.z, 0.2f * v0.z); v0.w = fmaxf(v0.w, 0.2f * v0.w);
    v1.x = fmaxf(v1.x, 0.2f * v1.x); v1.y = fmaxf(v1.y, 0.2f * v1.y);
    v1.z = fmaxf(v1.z, 0.2f * v1.z); v1.w = fmaxf(v1.w, 0.2f * v1.w);

    float4* Or = (float4*)(out + (size_t)row * Cc);
    Or[lane * 2]     = v0;
    Or[lane * 2 + 1] = v1;
}

// ---------------------------------------------------------------------------
extern "C" void kernel_launch(void* const* d_in, const int* in_sizes, int n_in,
                              void* d_out, int out_size) {
    const float* q    = (const float*)d_in[0];   // [4,8192,256]
    const float* qpos = (const float*)d_in[1];   // [4,8192,3]
    const float* W    = (const float*)d_in[2];   // [512,256]
    const float* bias = (const float*)d_in[3];   // [256]
    float* out = (float*)d_out;
    (void)in_sizes; (void)n_in; (void)out_size;

    cudaStream_t s2;
    cudaEvent_t eFork, eJoin;
    cudaStreamCreateWithFlags(&s2, cudaStreamNonBlocking);
    cudaEventCreateWithFlags(&eFork, cudaEventDisableTiming);
    cudaEventCreateWithFlags(&eJoin, cudaEventDisableTiming);

    cudaEventRecord(eFork, 0);
    cudaStreamWaitEvent(s2, eFork, 0);

    // --- side branch: GEMM chain ---
    prep_A_kernel<<<(ROWS * Cc / 4 + 255) / 256, 256, 0, s2>>>(q);
    prep_B_kernel<<<(Ff * Cc + 255) / 256, 256, 0, s2>>>(W);
    gemm_mma_kernel<<<dim3(ROWS / 128, Ff / 128), 256, 0, s2>>>();
    cudaEventRecord(eJoin, s2);

    // --- main branch: KNN chain ---
    prep_pos_kernel<<<(ROWS + 255) / 256, 256>>>(qpos);
    sort_kernel<<<Bn, 1024>>>();
    knn_kernel<<<dim3(Nn / 32, Bn), 256>>>();
    knn_fix_kernel<<<ROWS / 256, 256>>>();

    // --- join, then epilogue ---
    cudaStreamWaitEvent(0, eJoin, 0);
    gather_max_kernel<<<ROWS / 8, 256>>>(bias, out);
}

// round 17
// speedup vs baseline: 2.4353x; 1.0553x over previous
#include <cuda_runtime.h>
#include <cuda_bf16.h>
#include <cuda_fp16.h>
#include <float.h>
#include <stdint.h>

#define Bn   4
#define Nn   8192
#define Cc   256
#define Kk   16
#define Ff   512
#define ROWS (Bn*Nn)
#define CAP  128

__device__ float4 g_pos4 [ROWS];
__device__ float4 g_pos4s[ROWS];
__device__ int    g_sid  [ROWS];
__device__ int    g_ovf  [ROWS];
__device__ __half g_Ph[(size_t)ROWS * Cc];   // P = q@Wa   (fp16, gather-only)
__device__ float  g_U [(size_t)ROWS * Cc];   // U = q@(Wb-Wa)  (fp32)
__device__ int    g_idx[ROWS * Kk];
__device__ __nv_bfloat16 g_Ah[(size_t)ROWS * Cc];
__device__ __nv_bfloat16 g_Al[(size_t)ROWS * Cc];
__device__ __nv_bfloat16 g_Bh[Ff * Cc];   // B^T: [n][k]
__device__ __nv_bfloat16 g_Bl[Ff * Cc];

__device__ __forceinline__ uint32_t smem_u32(const void* p) {
    uint32_t a;
    asm("{ .reg .u64 t; cvta.to.shared.u64 t, %1; cvt.u32.u64 %0, t; }" : "=r"(a) : "l"(p));
    return a;
}
#define LDSM_X4(r, addr) \
    asm volatile("ldmatrix.sync.aligned.m8n8.x4.shared.b16 {%0,%1,%2,%3}, [%4];" \
        : "=r"((r)[0]), "=r"((r)[1]), "=r"((r)[2]), "=r"((r)[3]) : "r"(addr))
#define LDSM_X2(r, addr) \
    asm volatile("ldmatrix.sync.aligned.m8n8.x2.shared.b16 {%0,%1}, [%2];" \
        : "=r"((r)[0]), "=r"((r)[1]) : "r"(addr))
#define MMA_BF16(c, a, b) \
    asm volatile("mma.sync.aligned.m16n8k16.row.col.f32.bf16.bf16.f32 " \
        "{%0,%1,%2,%3}, {%4,%5,%6,%7}, {%8,%9}, {%0,%1,%2,%3};" \
        : "+f"((c)[0]), "+f"((c)[1]), "+f"((c)[2]), "+f"((c)[3]) \
        : "r"((a)[0]), "r"((a)[1]), "r"((a)[2]), "r"((a)[3]), "r"((b)[0]), "r"((b)[1]))

// ---------------------------------------------------------------------------
__global__ void prep_pos_kernel(const float* __restrict__ qpos) {
    int i = blockIdx.x * blockDim.x + threadIdx.x;
    if (i >= ROWS) return;
    float x = qpos[i*3+0], y = qpos[i*3+1], z = qpos[i*3+2];
    float n = fmaf(z, z, fmaf(y, y, x * x));
    g_pos4[i] = make_float4(x, y, z, n);
}

__global__ void prep_A_kernel(const float* __restrict__ q) {
    int i = blockIdx.x * 256 + threadIdx.x;
    if (i >= ROWS * Cc / 4) return;
    float4 v = ((const float4*)q)[i];
    __nv_bfloat16 h0 = __float2bfloat16(v.x), h1 = __float2bfloat16(v.y);
    __nv_bfloat16 h2 = __float2bfloat16(v.z), h3 = __float2bfloat16(v.w);
    __nv_bfloat16 l0 = __float2bfloat16(v.x - __bfloat162float(h0));
    __nv_bfloat16 l1 = __float2bfloat16(v.y - __bfloat162float(h1));
    __nv_bfloat16 l2 = __float2bfloat16(v.z - __bfloat162float(h2));
    __nv_bfloat16 l3 = __float2bfloat16(v.w - __bfloat162float(h3));
    uint2 hh, ll;
    hh.x = ((uint32_t)__bfloat16_as_ushort(h1) << 16) | __bfloat16_as_ushort(h0);
    hh.y = ((uint32_t)__bfloat16_as_ushort(h3) << 16) | __bfloat16_as_ushort(h2);
    ll.x = ((uint32_t)__bfloat16_as_ushort(l1) << 16) | __bfloat16_as_ushort(l0);
    ll.y = ((uint32_t)__bfloat16_as_ushort(l3) << 16) | __bfloat16_as_ushort(l2);
    ((uint2*)g_Ah)[i] = hh;
    ((uint2*)g_Al)[i] = ll;
}

__global__ void prep_B_kernel(const float* __restrict__ W) {
    int i = blockIdx.x * 256 + threadIdx.x;
    if (i >= Ff * Cc) return;
    int n = i >> 8;
    int k = i & 255;
    float v;
    if (n < Cc) v = W[k * Cc + n];
    else        v = W[(Cc + k) * Cc + (n - Cc)] - W[k * Cc + (n - Cc)];
    __nv_bfloat16 h = __float2bfloat16(v);
    __nv_bfloat16 l = __float2bfloat16(v - __bfloat162float(h));
    g_Bh[i] = h;
    g_Bl[i] = l;
}

// ---------------------------------------------------------------------------
__global__ __launch_bounds__(1024) void sort_kernel() {
    const int b   = blockIdx.x;
    const int tid = threadIdx.x;
    __shared__ unsigned sk[Nn];

    for (int i = tid; i < Nn; i += 1024) {
        unsigned u = __float_as_uint(g_pos4[b*Nn + i].x);
        u = (u & 0x80000000u) ? ~u : (u | 0x80000000u);
        sk[i] = (u & 0xFFFFE000u) | (unsigned)i;
    }
    __syncthreads();

    for (int k = 2; k <= Nn; k <<= 1) {
        for (int j = k >> 1; j > 0; j >>= 1) {
            for (int t = tid; t < Nn/2; t += 1024) {
                int i   = 2*t - (t & (j - 1));
                int ixj = i + j;
                unsigned a = sk[i], c = sk[ixj];
                bool asc = ((i & k) == 0);
                if ((a > c) == asc) { sk[i] = c; sk[ixj] = a; }
            }
            __syncthreads();
        }
    }

    for (int i = tid; i < Nn; i += 1024) {
        int orig = (int)(sk[i] & 8191u);
        g_pos4s[b*Nn + i] = g_pos4[b*Nn + orig];
        g_sid  [b*Nn + i] = orig;
    }
}

// ---------------------------------------------------------------------------
// KNN v6: v5 + per-warp in-tile x-window scan restriction.
// Tiles are x-sorted internally; candidates admissible for a warp form a
// contiguous j-range found via a 32-probe ballot (conservative, 32-granular).
// ---------------------------------------------------------------------------
__global__ __launch_bounds__(256) void knn_kernel() {
    const int b    = blockIdx.y;
    const int tid  = threadIdx.x;
    const int w    = tid >> 5;
    const int lane = tid & 31;
    const int qb   = blockIdx.x * 32 + w * 4;

    const float4* __restrict__ pos = g_pos4s + b * Nn;
    const int*    __restrict__ sid = g_sid   + b * Nn;

    __shared__ float4         tile[1024];
    __shared__ float          ad[32][CAP];
    __shared__ unsigned short ai[32][CAP];
    __shared__ int            acnt[32];
    __shared__ float          wthrt[8];

    float qx[4], qy[4], qz[4], qn[4];
#pragma unroll
    for (int i = 0; i < 4; ++i) {
        float4 m = pos[qb + i];
        qx[i] = m.x; qy[i] = m.y; qz[i] = m.z; qn[i] = m.w;
    }
    const float wqxlo = qx[0];
    const float wqxhi = qx[3];

    const int ctile = blockIdx.x >> 5;

    if (tid < 32) acnt[tid] = 0;
    {
        const int t0 = ctile * 1024;
#pragma unroll
        for (int j = 0; j < 4; ++j)
            tile[tid + j * 256] = pos[t0 + tid + j * 256];
    }
    __syncthreads();

    // ---- phase 1: per-lane top-2 per query over own tile (full scan) ----
    float t1[4], t2[4];
#pragma unroll
    for (int i = 0; i < 4; ++i) { t1[i] = FLT_MAX; t2[i] = FLT_MAX; }

    for (int m = 0; m < 32; m += 4) {
        float4 c0 = tile[lane + (m + 0) * 32];
        float4 c1 = tile[lane + (m + 1) * 32];
        float4 c2 = tile[lane + (m + 2) * 32];
        float4 c3 = tile[lane + (m + 3) * 32];
#pragma unroll
        for (int i = 0; i < 4; ++i) {
            float d0 = fmaf(-2.0f, fmaf(qz[i], c0.z, fmaf(qy[i], c0.y, qx[i] * c0.x)), c0.w);
            float d1 = fmaf(-2.0f, fmaf(qz[i], c1.z, fmaf(qy[i], c1.y, qx[i] * c1.x)), c1.w);
            float d2 = fmaf(-2.0f, fmaf(qz[i], c2.z, fmaf(qy[i], c2.y, qx[i] * c2.x)), c2.w);
            float d3 = fmaf(-2.0f, fmaf(qz[i], c3.z, fmaf(qy[i], c3.y, qx[i] * c3.x)), c3.w);
            float mn01 = fminf(d0, d1), mx01 = fmaxf(d0, d1);
            float mn23 = fminf(d2, d3), mx23 = fmaxf(d2, d3);
            float s1 = fminf(mn01, mn23);
            float s2 = fminf(fmaxf(mn01, mn23), fminf(mx01, mx23));
            float nt1 = fminf(t1[i], s1);
            t2[i] = fminf(fmaxf(t1[i], s1), fminf(t2[i], s2));
            t1[i] = nt1;
        }
    }

    float thr[4];
#pragma unroll
    for (int i = 0; i < 4; ++i) {
        float a = t1[i], bb = t2[i];
        float m = FLT_MAX;
        for (int r = 0; r < 16; ++r) {
            float lo = fminf(a, bb);
            m = lo;
            m = fminf(m, __shfl_xor_sync(0xffffffffu, m, 1));
            m = fminf(m, __shfl_xor_sync(0xffffffffu, m, 2));
            m = fminf(m, __shfl_xor_sync(0xffffffffu, m, 4));
            m = fminf(m, __shfl_xor_sync(0xffffffffu, m, 8));
            m = fminf(m, __shfl_xor_sync(0xffffffffu, m, 16));
            unsigned msk = __ballot_sync(0xffffffffu, lo == m);
            int leader = __ffs(msk) - 1;
            if (lane == leader) {
                if (a <= bb) a = FLT_MAX; else bb = FLT_MAX;
            }
        }
        thr[i] = m;
    }

    float mywt = fmaxf(fmaxf(thr[0] + qn[0], thr[1] + qn[1]),
                       fmaxf(thr[2] + qn[2], thr[3] + qn[3]));
    if (lane == 0) wthrt[w] = mywt;
    __syncthreads();
    float maxthr_true = wthrt[0];
#pragma unroll
    for (int i = 1; i < 8; ++i) maxthr_true = fmaxf(maxthr_true, wthrt[i]);

    const float bqxlo = pos[blockIdx.x * 32].x;
    const float bqxhi = pos[blockIdx.x * 32 + 31].x;

    // warp x-window (true-space radius bound)
    const float R    = sqrtf(mywt);
    const float wxlo = wqxlo - R;
    const float wxhi = wqxhi + R;

    // ---- phase 2: window-restricted append over non-skippable tiles ----
    for (int ot = 0; ot < 8; ++ot) {
        const int tt = (ctile + ot) & 7;
        const int t0 = tt * 1024;
        if (ot > 0) {
            // block-uniform load skip
            float gap = 0.0f;
            if (tt > ctile)      gap = pos[t0].x - bqxhi;
            else if (tt < ctile) gap = bqxlo - pos[t0 + 1023].x;
            if (gap > 0.0f && gap * gap > maxthr_true) continue;

            __syncthreads();
#pragma unroll
            for (int j = 0; j < 4; ++j)
                tile[tid + j * 256] = pos[t0 + tid + j * 256];
            __syncthreads();
        }

        // per-warp coarse j-window via strided probes + ballots (32-granular)
        {
            float probe = tile[lane * 32].x;
            unsigned blo = __ballot_sync(0xffffffffu, probe <  wxlo);
            unsigned bhi = __ballot_sync(0xffffffffu, probe <= wxhi);
            int p = __popc(blo);
            int qcnt = __popc(bhi);
            if (qcnt == 0) continue;                  // whole tile right of window
            int jlo = (p > 0) ? (p - 1) * 32 : 0;     // conservative
            int jhi = (qcnt < 32) ? qcnt * 32 - 1 : 1023;
            if (jlo > jhi) continue;
            int m0 = (jlo >> 7) * 4;
            int m1 = ((jhi >> 7) + 1) * 4;
            if (m1 > 32) m1 = 32;

            for (int m = m0; m < m1; m += 4) {
                float4 c0 = tile[lane + (m + 0) * 32];
                float4 c1 = tile[lane + (m + 1) * 32];
                float4 c2 = tile[lane + (m + 2) * 32];
                float4 c3 = tile[lane + (m + 3) * 32];
#pragma unroll
                for (int i = 0; i < 4; ++i) {
                    float d0 = fmaf(-2.0f, fmaf(qz[i], c0.z, fmaf(qy[i], c0.y, qx[i] * c0.x)), c0.w);
                    float d1 = fmaf(-2.0f, fmaf(qz[i], c1.z, fmaf(qy[i], c1.y, qx[i] * c1.x)), c1.w);
                    float d2 = fmaf(-2.0f, fmaf(qz[i], c2.z, fmaf(qy[i], c2.y, qx[i] * c2.x)), c2.w);
                    float d3 = fmaf(-2.0f, fmaf(qz[i], c3.z, fmaf(qy[i], c3.y, qx[i] * c3.x)), c3.w);
                    float mn = fminf(fminf(d0, d1), fminf(d2, d3));
                    if (mn <= thr[i]) {
                        const int ql = w * 4 + i;
                        const int jb = t0 + lane + m * 32;
                        if (d0 <= thr[i]) {
                            int sl = atomicAdd(&acnt[ql], 1);
                            if (sl < CAP) { ad[ql][sl] = d0; ai[ql][sl] = (unsigned short)(jb); }
                        }
                        if (d1 <= thr[i]) {
                            int sl = atomicAdd(&acnt[ql], 1);
                            if (sl < CAP) { ad[ql][sl] = d1; ai[ql][sl] = (unsigned short)(jb + 32); }
                        }
                        if (d2 <= thr[i]) {
                            int sl = atomicAdd(&acnt[ql], 1);
                            if (sl < CAP) { ad[ql][sl] = d2; ai[ql][sl] = (unsigned short)(jb + 64); }
                        }
                        if (d3 <= thr[i]) {
                            int sl = atomicAdd(&acnt[ql], 1);
                            if (sl < CAP) { ad[ql][sl] = d3; ai[ql][sl] = (unsigned short)(jb + 96); }
                        }
                    }
                }
            }
        }
    }
    __syncthreads();

    if (tid < 32) {
        const int cntRaw = acnt[tid];
        const int cnt    = cntRaw < CAP ? cntRaw : CAP;
        float md[Kk]; int mi[Kk];
#pragma unroll
        for (int i = 0; i < Kk; ++i) { md[i] = FLT_MAX; mi[i] = 0; }
        float mthr = FLT_MAX;
        for (int t = 0; t < cnt; ++t) {
            float cd = ad[tid][t];
            if (cd < mthr) {
                int ci = ai[tid][t];
#pragma unroll
                for (int u = 0; u < Kk; ++u) {
                    bool  sw = cd < md[u];
                    float od = md[u]; int oi = mi[u];
                    md[u] = sw ? cd : od;  mi[u] = sw ? ci : oi;
                    cd    = sw ? od : cd;  ci    = sw ? oi : ci;
                }
                mthr = md[Kk - 1];
            }
        }
        const int orig = sid[blockIdx.x * 32 + tid];
        const int gq   = b * Nn + orig;
        g_ovf[gq] = (cntRaw > CAP) ? 1 : 0;
#pragma unroll
        for (int i = 0; i < Kk; ++i) g_idx[gq * Kk + i] = sid[mi[i]];
    }
}

// ---------------------------------------------------------------------------
__global__ __launch_bounds__(256) void knn_fix_kernel() {
    const int i = blockIdx.x * 256 + threadIdx.x;
    if (i >= ROWS) return;
    if (!g_ovf[i]) return;
    const int b = i >> 13;
    const float4* __restrict__ pos = g_pos4 + b * Nn;
    float4 me = pos[i & 8191];
    const float qx = me.x, qy = me.y, qz = me.z;
    float dist[Kk]; int nid[Kk];
#pragma unroll
    for (int t = 0; t < Kk; ++t) { dist[t] = FLT_MAX; nid[t] = 0; }
    float thr = FLT_MAX;
    for (int j = 0; j < Nn; ++j) {
        float4 cp = pos[j];
        float d2 = fmaf(-2.0f, fmaf(qz, cp.z, fmaf(qy, cp.y, qx * cp.x)), cp.w);
        if (d2 < thr) {
            float cd = d2; int ci = j;
#pragma unroll
            for (int t = 0; t < Kk; ++t) {
                bool  sw = cd < dist[t];
                float od = dist[t]; int oi = nid[t];
                dist[t] = sw ? cd : od;  nid[t] = sw ? ci : oi;
                cd      = sw ? od : cd;  ci     = sw ? oi : ci;
            }
            thr = dist[Kk - 1];
        }
    }
#pragma unroll
    for (int t = 0; t < Kk; ++t) g_idx[i * Kk + t] = nid[t];
}

// ---------------------------------------------------------------------------
// bf16-split GEMM via warp-level mma.sync (HMMA).
// Epilogue: P columns (bn0 < 256) -> g_Ph as fp16; U columns -> g_U as fp32.
// ---------------------------------------------------------------------------
__global__ __launch_bounds__(256) void gemm_mma_kernel() {
    __shared__ __nv_bfloat16 sAh[128][40];
    __shared__ __nv_bfloat16 sAl[128][40];
    __shared__ __nv_bfloat16 sBh[128][40];
    __shared__ __nv_bfloat16 sBl[128][40];

    const int tid  = threadIdx.x;
    const int wid  = tid >> 5;
    const int lane = tid & 31;
    const int wm   = wid >> 2;
    const int wn   = wid & 3;
    const int bm0  = blockIdx.x * 128;
    const int bn0  = blockIdx.y * 128;

    float acc[4][4][4];
#pragma unroll
    for (int mt = 0; mt < 4; ++mt)
#pragma unroll
        for (int nt = 0; nt < 4; ++nt)
#pragma unroll
            for (int i = 0; i < 4; ++i) acc[mt][nt][i] = 0.0f;

    const int a_sub = lane >> 3, a_r = lane & 7;
    const int a_row_off = (a_sub & 1) * 8 + a_r;
    const int a_col_off = (a_sub >> 1) * 8;
    const int b_sub = (lane >> 3) & 1, b_r = lane & 7;

    for (int kt = 0; kt < 8; ++kt) {
        const int k0 = kt * 32;
#pragma unroll
        for (int half = 0; half < 2; ++half) {
            const int gi  = tid + half * 256;
            const int row = gi >> 2;
            const int g   = gi & 3;
            const size_t aoff = (size_t)(bm0 + row) * Cc + k0 + g * 8;
            const size_t boff = (size_t)(bn0 + row) * Cc + k0 + g * 8;
            *(uint4*)&sAh[row][g * 8] = *(const uint4*)(g_Ah + aoff);
            *(uint4*)&sAl[row][g * 8] = *(const uint4*)(g_Al + aoff);
            *(uint4*)&sBh[row][g * 8] = *(const uint4*)(g_Bh + boff);
            *(uint4*)&sBl[row][g * 8] = *(const uint4*)(g_Bl + boff);
        }
        __syncthreads();

#pragma unroll
        for (int kh = 0; kh < 32; kh += 16) {
            uint32_t ah[4][4], al[4][4], bh[4][2], bl[4][2];
#pragma unroll
            for (int mt = 0; mt < 4; ++mt) {
                const int arow = wm * 64 + mt * 16 + a_row_off;
                const int acol = kh + a_col_off;
                LDSM_X4(ah[mt], smem_u32(&sAh[arow][acol]));
                LDSM_X4(al[mt], smem_u32(&sAl[arow][acol]));
            }
#pragma unroll
            for (int nt = 0; nt < 4; ++nt) {
                const int brow = wn * 32 + nt * 8 + b_r;
                const int bcol = kh + b_sub * 8;
                LDSM_X2(bh[nt], smem_u32(&sBh[brow][bcol]));
                LDSM_X2(bl[nt], smem_u32(&sBl[brow][bcol]));
            }
#pragma unroll
            for (int mt = 0; mt < 4; ++mt)
#pragma unroll
                for (int nt = 0; nt < 4; ++nt) {
                    MMA_BF16(acc[mt][nt], ah[mt], bh[nt]);
                    MMA_BF16(acc[mt][nt], ah[mt], bl[nt]);
                    MMA_BF16(acc[mt][nt], al[mt], bh[nt]);
                }
        }
        __syncthreads();
    }

    const int g   = lane >> 2;
    const int tig = lane & 3;
    if (bn0 < Cc) {
#pragma unroll
        for (int mt = 0; mt < 4; ++mt)
#pragma unroll
            for (int nt = 0; nt < 4; ++nt) {
                const int row = bm0 + wm * 64 + mt * 16 + g;
                const int col = bn0 + wn * 32 + nt * 8 + tig * 2;
                __half2 h0 = __floats2half2_rn(acc[mt][nt][0], acc[mt][nt][1]);
                __half2 h1 = __floats2half2_rn(acc[mt][nt][2], acc[mt][nt][3]);
                *(__half2*)(g_Ph + (size_t)row * Cc + col)       = h0;
                *(__half2*)(g_Ph + (size_t)(row + 8) * Cc + col) = h1;
            }
    } else {
#pragma unroll
        for (int mt = 0; mt < 4; ++mt)
#pragma unroll
            for (int nt = 0; nt < 4; ++nt) {
                const int row = bm0 + wm * 64 + mt * 16 + g;
                const int col = (bn0 - Cc) + wn * 32 + nt * 8 + tig * 2;
                float2 v0 = make_float2(acc[mt][nt][0], acc[mt][nt][1]);
                float2 v1 = make_float2(acc[mt][nt][2], acc[mt][nt][3]);
                *(float2*)(g_U + (size_t)row * Cc + col)       = v0;
                *(float2*)(g_U + (size_t)(row + 8) * Cc + col) = v1;
            }
    }
}

// ---------------------------------------------------------------------------
__global__ __launch_bounds__(256) void gather_max_kernel(const float* __restrict__ bias,
                                                         float* __restrict__ out) {
    const int row  = blockIdx.x * 8 + (threadIdx.x >> 5);
    const int lane = threadIdx.x & 31;
    const int b    = row >> 13;

    const int* ir = g_idx + row * Kk;
    int myn = ir[lane & (Kk - 1)];

    const __half* Pbase = g_Ph + (size_t)(b << 13) * Cc;

    __half2 m0 = __floats2half2_rn(-65504.f, -65504.f);
    __half2 m1 = m0, m2 = m0, m3 = m0;

#pragma unroll
    for (int j = 0; j < Kk; ++j) {
        int nb = __shfl_sync(0xffffffffu, myn, j);
        uint4 v = ((const uint4*)(Pbase + (size_t)nb * Cc))[lane];
        m0 = __hmax2(m0, *reinterpret_cast<__half2*>(&v.x));
        m1 = __hmax2(m1, *reinterpret_cast<__half2*>(&v.y));
        m2 = __hmax2(m2, *reinterpret_cast<__half2*>(&v.z));
        m3 = __hmax2(m3, *reinterpret_cast<__half2*>(&v.w));
    }

    float2 f0 = __half22float2(m0), f1 = __half22float2(m1);
    float2 f2 = __half22float2(m2), f3 = __half22float2(m3);

    const float4* Ur = (const float4*)(g_U + (size_t)row * Cc);
    float4 u0 = Ur[lane * 2], u1 = Ur[lane * 2 + 1];
    const float4* Br = (const float4*)bias;
    float4 bb0 = Br[lane * 2], bb1 = Br[lane * 2 + 1];

    float4 v0, v1;
    v0.x = f0.x + u0.x + bb0.x; v0.y = f0.y + u0.y + bb0.y;
    v0.z = f1.x + u0.z + bb0.z; v0.w = f1.y + u0.w + bb0.w;
    v1.x = f2.x + u1.x + bb1.x; v1.y = f2.y + u1.y + bb1.y;
    v1.z = f3.x + u1.z + bb1.z; v1.w = f3.y + u1.w + bb1.w;

    v0.x = fmaxf(v0.x, 0.2f * v0.x); v0.y = fmaxf(v0.y, 0.2f * v0.y);
    v0.z = fmaxf(v0.z, 0.2f * v0.z); v0.w = fmaxf(v0.w, 0.2f * v0.w);
    v1.x = fmaxf(v1.x, 0.2f * v1.x); v1.y = fmaxf(v1.y, 0.2f * v1.y);
    v1.z = fmaxf(v1.z, 0.2f * v1.z); v1.w = fmaxf(v1.w, 0.2f * v1.w);

    float4* Or = (float4*)(out + (size_t)row * Cc);
    Or[lane * 2]     = v0;
    Or[lane * 2 + 1] = v1;
}

// ---------------------------------------------------------------------------
extern "C" void kernel_launch(void* const* d_in, const int* in_sizes, int n_in,
                              void* d_out, int out_size) {
    const float* q    = (const float*)d_in[0];   // [4,8192,256]
    const float* qpos = (const float*)d_in[1];   // [4,8192,3]
    const float* W    = (const float*)d_in[2];   // [512,256]
    const float* bias = (const float*)d_in[3];   // [256]
    float* out = (float*)d_out;
    (void)in_sizes; (void)n_in; (void)out_size;

    cudaStream_t s2;
    cudaEvent_t eFork, eJoin;
    cudaStreamCreateWithFlags(&s2, cudaStreamNonBlocking);
    cudaEventCreateWithFlags(&eFork, cudaEventDisableTiming);
    cudaEventCreateWithFlags(&eJoin, cudaEventDisableTiming);

    cudaEventRecord(eFork, 0);
    cudaStreamWaitEvent(s2, eFork, 0);

    // --- side branch: GEMM chain ---
    prep_A_kernel<<<(ROWS * Cc / 4 + 255) / 256, 256, 0, s2>>>(q);
    prep_B_kernel<<<(Ff * Cc + 255) / 256, 256, 0, s2>>>(W);
    gemm_mma_kernel<<<dim3(ROWS / 128, Ff / 128), 256, 0, s2>>>();
    cudaEventRecord(eJoin, s2);

    // --- main branch: KNN chain ---
    prep_pos_kernel<<<(ROWS + 255) / 256, 256>>>(qpos);
    sort_kernel<<<Bn, 1024>>>();
    knn_kernel<<<dim3(Nn / 32, Bn), 256>>>();
    knn_fix_kernel<<<ROWS / 256, 256>>>();

    // --- join, then epilogue ---
    cudaStreamWaitEvent(0, eJoin, 0);
    gather_max_kernel<<<ROWS / 8, 256>>>(bias, out);
}